// round 5
// baseline (speedup 1.0000x reference)
#include <cuda_runtime.h>
#include <math.h>

// Problem constants
#define SEQ   2048
#define DMODEL 1024
#define NH    16
#define NKVH  4
#define HDIM  64
#define LATD  256
#define WINSZ 256

// ---------------------------------------------------------------------------
// Scratch (device globals; no allocation allowed)
// ---------------------------------------------------------------------------
__device__ float g_x1  [SEQ * DMODEL];   // rmsnorm output
__device__ float g_q   [SEQ * DMODEL];   // Q (16 heads x 64)
__device__ float g_lat [SEQ * LATD];     // latent
__device__ float g_k   [SEQ * LATD];     // K (4 heads x 64)
__device__ float g_v   [SEQ * LATD];     // V (4 heads x 64)
__device__ float g_attn[SEQ * DMODEL];   // merged attention output

// ---------------------------------------------------------------------------
// RMSNorm: one block per row, 256 threads, float4 per thread (D=1024)
// ---------------------------------------------------------------------------
__global__ void rmsnorm_kernel(const float* __restrict__ x,
                               const float* __restrict__ w,
                               float* __restrict__ y) {
    int row = blockIdx.x;
    int tid = threadIdx.x;
    const float4* xr = (const float4*)(x + (size_t)row * DMODEL);
    float4 v = xr[tid];
    float ss = v.x * v.x + v.y * v.y + v.z * v.z + v.w * v.w;
    __shared__ float red[256];
    red[tid] = ss;
    __syncthreads();
    #pragma unroll
    for (int o = 128; o > 0; o >>= 1) {
        if (tid < o) red[tid] += red[tid + o];
        __syncthreads();
    }
    float r = rsqrtf(red[0] / (float)DMODEL + 1e-6f);
    float4 wv = ((const float4*)w)[tid];
    float4 o4 = make_float4(v.x * r * wv.x, v.y * r * wv.y,
                            v.z * r * wv.z, v.w * r * wv.w);
    ((float4*)(y + (size_t)row * DMODEL))[tid] = o4;
}

// ---------------------------------------------------------------------------
// SGEMM: C[M,N] = A[M,K] @ B[K,N] (+ R[M,N] if R != null)
// 64x64 tile per block, BK=16, 256 threads, 4x4 register micro-tile.
// Assumes M%64==0, N%64==0, K%16==0 (true for all shapes here).
// ---------------------------------------------------------------------------
__global__ void sgemm_kernel(const float* __restrict__ A,
                             const float* __restrict__ B,
                             const float* __restrict__ R,
                             float* __restrict__ C,
                             int N, int K) {
    __shared__ __align__(16) float As[16][64];
    __shared__ __align__(16) float Bs[16][64];

    int tid = threadIdx.x;
    int r0 = blockIdx.y * 64;
    int c0 = blockIdx.x * 64;

    int ar = tid >> 2;            // 0..63
    int ac = (tid & 3) << 2;      // 0,4,8,12
    int br = tid >> 4;            // 0..15
    int bc = (tid & 15) << 2;     // 0..60
    int tr = tid >> 4;            // 0..15
    int tc = tid & 15;            // 0..15

    float acc[4][4];
    #pragma unroll
    for (int i = 0; i < 4; i++)
        #pragma unroll
        for (int j = 0; j < 4; j++) acc[i][j] = 0.0f;

    for (int k0 = 0; k0 < K; k0 += 16) {
        float4 a4 = *(const float4*)(A + (size_t)(r0 + ar) * K + k0 + ac);
        As[ac + 0][ar] = a4.x;
        As[ac + 1][ar] = a4.y;
        As[ac + 2][ar] = a4.z;
        As[ac + 3][ar] = a4.w;
        *(float4*)&Bs[br][bc] =
            *(const float4*)(B + (size_t)(k0 + br) * N + c0 + bc);
        __syncthreads();

        #pragma unroll
        for (int kk = 0; kk < 16; kk++) {
            float4 av = *(const float4*)&As[kk][tr << 2];
            float4 bv = *(const float4*)&Bs[kk][tc << 2];
            float a[4] = {av.x, av.y, av.z, av.w};
            float b[4] = {bv.x, bv.y, bv.z, bv.w};
            #pragma unroll
            for (int i = 0; i < 4; i++)
                #pragma unroll
                for (int j = 0; j < 4; j++)
                    acc[i][j] += a[i] * b[j];
        }
        __syncthreads();
    }

    #pragma unroll
    for (int i = 0; i < 4; i++) {
        int row = r0 + (tr << 2) + i;
        size_t off = (size_t)row * N + c0 + (tc << 2);
        float4 rv = make_float4(0.f, 0.f, 0.f, 0.f);
        if (R) rv = *(const float4*)(R + off);
        float4 o = make_float4(acc[i][0] + rv.x, acc[i][1] + rv.y,
                               acc[i][2] + rv.z, acc[i][3] + rv.w);
        *(float4*)(C + off) = o;
    }
}

// ---------------------------------------------------------------------------
// Fused RoPE (interleaved pairs) + qk_norm (rmsnorm without weight, hd=64).
// Grid: (SEQ, nheads), 32 threads (one pair per lane).
// ---------------------------------------------------------------------------
__global__ void rope_qknorm_kernel(float* __restrict__ x, int nheads, float base) {
    int s = blockIdx.x;
    int h = blockIdx.y;
    int i = threadIdx.x;  // pair index 0..31
    float* p = x + (size_t)s * nheads * HDIM + h * HDIM;

    float invf = powf(base, -((float)(2 * i) / (float)HDIM));
    float ang = (float)s * invf;
    float sn, cs;
    sincosf(ang, &sn, &cs);

    float xe = p[2 * i];
    float xo = p[2 * i + 1];
    float re = xe * cs - xo * sn;
    float ro = xe * sn + xo * cs;

    float ss = re * re + ro * ro;
    #pragma unroll
    for (int o = 16; o > 0; o >>= 1)
        ss += __shfl_xor_sync(0xffffffffu, ss, o);

    float r = rsqrtf(ss / (float)HDIM + 1e-6f);
    p[2 * i]     = re * r;
    p[2 * i + 1] = ro * r;
}

// ---------------------------------------------------------------------------
// Attention: one block per (query s, q-head h). 128 threads.
// win == 0 -> full causal; win > 0 -> sliding window [s-win+1, s].
// Q: [SEQ, NH*64], K/V: [SEQ, NKVH*64], O: [SEQ, NH*64]
// Two-pass softmax with scores staged in SMEM.
// ---------------------------------------------------------------------------
__global__ void attn_kernel(const float* __restrict__ Q,
                            const float* __restrict__ K,
                            const float* __restrict__ V,
                            float* __restrict__ O,
                            int win) {
    int s = blockIdx.x;
    int h = blockIdx.y;
    int kvh = h >> 2;   // jnp.repeat: q head h uses kv head h/4
    int tid = threadIdx.x;

    __shared__ float qs[HDIM];
    __shared__ float sc[SEQ];
    __shared__ float red[128];

    int jstart = 0;
    if (win > 0) {
        jstart = s - win + 1;
        if (jstart < 0) jstart = 0;
    }
    int nk = s - jstart + 1;

    if (tid < HDIM)
        qs[tid] = Q[(size_t)s * DMODEL + h * HDIM + tid];
    __syncthreads();

    // Pass 1: scores + local max
    float mx = -1e30f;
    for (int j = tid; j < nk; j += 128) {
        const float* kr = K + (size_t)(jstart + j) * LATD + kvh * HDIM;
        float d = 0.0f;
        #pragma unroll
        for (int t = 0; t < HDIM; t += 4) {
            float4 k4 = *(const float4*)(kr + t);
            d += qs[t] * k4.x + qs[t + 1] * k4.y +
                 qs[t + 2] * k4.z + qs[t + 3] * k4.w;
        }
        d *= 0.125f;  // 1/sqrt(64)
        sc[j] = d;
        mx = fmaxf(mx, d);
    }
    red[tid] = mx;
    __syncthreads();
    #pragma unroll
    for (int o = 64; o > 0; o >>= 1) {
        if (tid < o) red[tid] = fmaxf(red[tid], red[tid + o]);
        __syncthreads();
    }
    mx = red[0];
    __syncthreads();

    // Pass 2: exp + sum
    float lsum = 0.0f;
    for (int j = tid; j < nk; j += 128) {
        float e = __expf(sc[j] - mx);
        sc[j] = e;
        lsum += e;
    }
    red[tid] = lsum;
    __syncthreads();
    #pragma unroll
    for (int o = 64; o > 0; o >>= 1) {
        if (tid < o) red[tid] += red[tid + o];
        __syncthreads();
    }
    float inv = 1.0f / red[0];
    __syncthreads();

    // Pass 3: P @ V, split j over two halves of the block
    int d = tid & 63;
    int half = tid >> 6;
    float acc = 0.0f;
    for (int j = half; j < nk; j += 2)
        acc += sc[j] * V[(size_t)(jstart + j) * LATD + kvh * HDIM + d];
    red[tid] = acc;
    __syncthreads();
    if (tid < HDIM)
        O[(size_t)s * DMODEL + h * HDIM + d] = (red[tid] + red[tid + 64]) * inv;
}

// ---------------------------------------------------------------------------
// Launch
// ---------------------------------------------------------------------------
extern "C" void kernel_launch(void* const* d_in, const int* in_sizes, int n_in,
                              void* d_out, int out_size) {
    (void)in_sizes; (void)n_in; (void)out_size;

    const float* hidden    = (const float*)d_in[0];
    const float* norm1_w   = (const float*)d_in[1];
    const float* norm2_w   = (const float*)d_in[2];
    const float* w_g_wq    = (const float*)d_in[3];
    const float* w_g_kvdn  = (const float*)d_in[4];
    const float* w_g_k_up  = (const float*)d_in[5];
    const float* w_g_v_up  = (const float*)d_in[6];
    const float* w_g_wo    = (const float*)d_in[7];
    const float* w_l_wq    = (const float*)d_in[8];
    const float* w_l_wk    = (const float*)d_in[9];
    const float* w_l_wv    = (const float*)d_in[10];
    const float* w_l_wo    = (const float*)d_in[11];
    float* out = (float*)d_out;

    float *x1, *q, *lat, *k, *v, *attn;
    cudaGetSymbolAddress((void**)&x1,   g_x1);
    cudaGetSymbolAddress((void**)&q,    g_q);
    cudaGetSymbolAddress((void**)&lat,  g_lat);
    cudaGetSymbolAddress((void**)&k,    g_k);
    cudaGetSymbolAddress((void**)&v,    g_v);
    cudaGetSymbolAddress((void**)&attn, g_attn);

    dim3 gemmGridD(DMODEL / 64, SEQ / 64);   // N=1024
    dim3 gemmGridL(LATD / 64,   SEQ / 64);   // N=256

    // ---- Layer 1: global latent attention ----
    rmsnorm_kernel<<<SEQ, 256>>>(hidden, norm1_w, x1);
    sgemm_kernel<<<gemmGridD, 256>>>(x1,  w_g_wq,   nullptr, q,   DMODEL, DMODEL);
    sgemm_kernel<<<gemmGridL, 256>>>(x1,  w_g_kvdn, nullptr, lat, LATD,   DMODEL);
    sgemm_kernel<<<gemmGridL, 256>>>(lat, w_g_k_up, nullptr, k,   LATD,   LATD);
    sgemm_kernel<<<gemmGridL, 256>>>(lat, w_g_v_up, nullptr, v,   LATD,   LATD);
    rope_qknorm_kernel<<<dim3(SEQ, NH),   32>>>(q, NH,   1000000.0f);
    rope_qknorm_kernel<<<dim3(SEQ, NKVH), 32>>>(k, NKVH, 1000000.0f);
    attn_kernel<<<dim3(SEQ, NH), 128>>>(q, k, v, attn, /*win=*/0);
    // out = attn @ g_wo + hidden
    sgemm_kernel<<<gemmGridD, 256>>>(attn, w_g_wo, hidden, out, DMODEL, DMODEL);

    // ---- Layer 2: local GQA attention ----
    rmsnorm_kernel<<<SEQ, 256>>>(out, norm2_w, x1);
    sgemm_kernel<<<gemmGridD, 256>>>(x1, w_l_wq, nullptr, q, DMODEL, DMODEL);
    sgemm_kernel<<<gemmGridL, 256>>>(x1, w_l_wk, nullptr, k, LATD,   DMODEL);
    sgemm_kernel<<<gemmGridL, 256>>>(x1, w_l_wv, nullptr, v, LATD,   DMODEL);
    rope_qknorm_kernel<<<dim3(SEQ, NH),   32>>>(q, NH,   10000.0f);
    rope_qknorm_kernel<<<dim3(SEQ, NKVH), 32>>>(k, NKVH, 10000.0f);
    attn_kernel<<<dim3(SEQ, NH), 128>>>(q, k, v, attn, /*win=*/WINSZ);
    // out = attn @ l_wo + out   (read-before-write per element: safe)
    sgemm_kernel<<<gemmGridD, 256>>>(attn, w_l_wo, out, out, DMODEL, DMODEL);
}

// round 6
// speedup vs baseline: 3.7818x; 3.7818x over previous
#include <cuda_runtime.h>
#include <math.h>

#define SEQ    2048
#define DMODEL 1024
#define NH     16
#define NKVH   4
#define HDIM   64
#define LATD   256
#define WINSZ  256

// ---------------------------------------------------------------------------
// Scratch (device globals; no allocation allowed)
// ---------------------------------------------------------------------------
__device__ float g_x1  [SEQ * DMODEL];
__device__ float g_q   [SEQ * DMODEL];
__device__ float g_lat [SEQ * LATD];
__device__ float g_k   [SEQ * LATD];
__device__ float g_v   [SEQ * LATD];
__device__ float g_attn[SEQ * DMODEL];

// ---------------------------------------------------------------------------
// RMSNorm: one block per row, 256 threads, float4 per thread (D=1024)
// ---------------------------------------------------------------------------
__global__ void rmsnorm_kernel(const float* __restrict__ x,
                               const float* __restrict__ w,
                               float* __restrict__ y) {
    int row = blockIdx.x;
    int tid = threadIdx.x;
    const float4* xr = (const float4*)(x + (size_t)row * DMODEL);
    float4 v = xr[tid];
    float ss = v.x * v.x + v.y * v.y + v.z * v.z + v.w * v.w;
    __shared__ float red[256];
    red[tid] = ss;
    __syncthreads();
    #pragma unroll
    for (int o = 128; o > 0; o >>= 1) {
        if (tid < o) red[tid] += red[tid + o];
        __syncthreads();
    }
    float r = rsqrtf(red[0] / (float)DMODEL + 1e-6f);
    float4 wv = ((const float4*)w)[tid];
    float4 o4 = make_float4(v.x * r * wv.x, v.y * r * wv.y,
                            v.z * r * wv.z, v.w * r * wv.w);
    ((float4*)(y + (size_t)row * DMODEL))[tid] = o4;
}

// ---------------------------------------------------------------------------
// SGEMM template: C[M,N] = A[M,K] @ B[K,N] (+ R if non-null)
// BMxBN tile per block, BK=16, 256 threads, double-buffered SMEM.
// Micro-tile: (BM/16)x(BN/16) per thread, in 4-wide spans.
// Requires M%BM==0, N%BN==0, K%16==0.
// ---------------------------------------------------------------------------
template<int BM, int BN>
__global__ __launch_bounds__(256, 1)
void sgemm_tpl(const float* __restrict__ A, const float* __restrict__ B,
               const float* __restrict__ R, float* __restrict__ C,
               int N, int K) {
    constexpr int RS  = BM / 64;          // row spans of 4
    constexpr int CS  = BN / 64;          // col spans of 4
    constexpr int AP  = BM + 4;           // padded pitch for transposed A
    constexpr int ALD = BM * 4 / 256;     // float4 A-loads per thread
    constexpr int BLD = BN * 4 / 256;     // float4 B-loads per thread
    constexpr int BF4 = BN / 4;           // float4s per B row

    __shared__ float As[2][16][AP];
    __shared__ float Bs[2][16][BN];

    int tid = threadIdx.x;
    int r0 = blockIdx.y * BM;
    int c0 = blockIdx.x * BN;
    int tr = tid >> 4;
    int tc = tid & 15;

    float acc[RS * 4][CS * 4];
    #pragma unroll
    for (int i = 0; i < RS * 4; i++)
        #pragma unroll
        for (int j = 0; j < CS * 4; j++) acc[i][j] = 0.0f;

    // prologue: load k-block 0 into buffer 0
    #pragma unroll
    for (int t = 0; t < ALD; t++) {
        int idx = tid + t * 256;
        int arow = idx >> 2;
        int ac4  = (idx & 3) << 2;
        float4 a = *(const float4*)(A + (size_t)(r0 + arow) * K + ac4);
        As[0][ac4 + 0][arow] = a.x;
        As[0][ac4 + 1][arow] = a.y;
        As[0][ac4 + 2][arow] = a.z;
        As[0][ac4 + 3][arow] = a.w;
    }
    #pragma unroll
    for (int t = 0; t < BLD; t++) {
        int idx = tid + t * 256;
        int brow = idx / BF4;
        int bcol = (idx % BF4) * 4;
        *(float4*)&Bs[0][brow][bcol] =
            *(const float4*)(B + (size_t)brow * N + c0 + bcol);
    }
    __syncthreads();

    int NKB = K >> 4;
    int cur = 0;
    for (int kb = 0; kb < NKB; kb++) {
        float4 pa[ALD], pb[BLD];
        bool more = (kb + 1 < NKB);
        int k0n = (kb + 1) << 4;
        if (more) {
            #pragma unroll
            for (int t = 0; t < ALD; t++) {
                int idx = tid + t * 256;
                int arow = idx >> 2;
                int ac4  = (idx & 3) << 2;
                pa[t] = *(const float4*)(A + (size_t)(r0 + arow) * K + k0n + ac4);
            }
            #pragma unroll
            for (int t = 0; t < BLD; t++) {
                int idx = tid + t * 256;
                int brow = idx / BF4;
                int bcol = (idx % BF4) * 4;
                pb[t] = *(const float4*)(B + (size_t)(k0n + brow) * N + c0 + bcol);
            }
        }

        #pragma unroll
        for (int kk = 0; kk < 16; kk++) {
            float a[RS * 4], b[CS * 4];
            #pragma unroll
            for (int rs = 0; rs < RS; rs++) {
                float4 av = *(const float4*)&As[cur][kk][rs * 64 + (tr << 2)];
                a[rs * 4 + 0] = av.x; a[rs * 4 + 1] = av.y;
                a[rs * 4 + 2] = av.z; a[rs * 4 + 3] = av.w;
            }
            #pragma unroll
            for (int cs = 0; cs < CS; cs++) {
                float4 bv = *(const float4*)&Bs[cur][kk][cs * 64 + (tc << 2)];
                b[cs * 4 + 0] = bv.x; b[cs * 4 + 1] = bv.y;
                b[cs * 4 + 2] = bv.z; b[cs * 4 + 3] = bv.w;
            }
            #pragma unroll
            for (int i = 0; i < RS * 4; i++)
                #pragma unroll
                for (int j = 0; j < CS * 4; j++)
                    acc[i][j] += a[i] * b[j];
        }

        if (more) {
            int nxt = cur ^ 1;
            #pragma unroll
            for (int t = 0; t < ALD; t++) {
                int idx = tid + t * 256;
                int arow = idx >> 2;
                int ac4  = (idx & 3) << 2;
                As[nxt][ac4 + 0][arow] = pa[t].x;
                As[nxt][ac4 + 1][arow] = pa[t].y;
                As[nxt][ac4 + 2][arow] = pa[t].z;
                As[nxt][ac4 + 3][arow] = pa[t].w;
            }
            #pragma unroll
            for (int t = 0; t < BLD; t++) {
                int idx = tid + t * 256;
                int brow = idx / BF4;
                int bcol = (idx % BF4) * 4;
                *(float4*)&Bs[nxt][brow][bcol] = pb[t];
            }
            __syncthreads();
            cur = nxt;
        }
    }

    #pragma unroll
    for (int rs = 0; rs < RS; rs++) {
        #pragma unroll
        for (int i = 0; i < 4; i++) {
            int row = r0 + rs * 64 + (tr << 2) + i;
            #pragma unroll
            for (int cs = 0; cs < CS; cs++) {
                size_t off = (size_t)row * N + c0 + cs * 64 + (tc << 2);
                float4 rv = make_float4(0.f, 0.f, 0.f, 0.f);
                if (R) rv = *(const float4*)(R + off);
                int ii = rs * 4 + i;
                float4 o = make_float4(acc[ii][cs * 4 + 0] + rv.x,
                                       acc[ii][cs * 4 + 1] + rv.y,
                                       acc[ii][cs * 4 + 2] + rv.z,
                                       acc[ii][cs * 4 + 3] + rv.w);
                *(float4*)(C + off) = o;
            }
        }
    }
}

// ---------------------------------------------------------------------------
// Fused RoPE + qk_norm (hd=64). Grid: (SEQ, nheads), 32 threads.
// ---------------------------------------------------------------------------
__global__ void rope_qknorm_kernel(float* __restrict__ x, int nheads, float base) {
    int s = blockIdx.x;
    int h = blockIdx.y;
    int i = threadIdx.x;
    float* p = x + (size_t)s * nheads * HDIM + h * HDIM;

    float invf = powf(base, -((float)(2 * i) / (float)HDIM));
    float ang = (float)s * invf;
    float sn, cs;
    sincosf(ang, &sn, &cs);

    float xe = p[2 * i];
    float xo = p[2 * i + 1];
    float re = xe * cs - xo * sn;
    float ro = xe * sn + xo * cs;

    float ss = re * re + ro * ro;
    #pragma unroll
    for (int o = 16; o > 0; o >>= 1)
        ss += __shfl_xor_sync(0xffffffffu, ss, o);

    float r = rsqrtf(ss / (float)HDIM + 1e-6f);
    p[2 * i]     = re * r;
    p[2 * i + 1] = ro * r;
}

// ---------------------------------------------------------------------------
// Flash-style attention: block per (64-query tile, head). 256 threads.
// Online softmax, K/V tiles of 64 streamed through SMEM.
// win==0 -> causal; win>0 -> sliding window [q-win+1, q].
// Dynamic smem: Qs[64][68] + Ks[64][68] + Ps[64][68] + Vs[64][64]
// ---------------------------------------------------------------------------
#define QS_PITCH 68
__global__ __launch_bounds__(256, 1)
void fattn_kernel(const float* __restrict__ Q, const float* __restrict__ K,
                  const float* __restrict__ V, float* __restrict__ O,
                  int win) {
    extern __shared__ float sm[];
    float (*Qs)[QS_PITCH] = (float(*)[QS_PITCH])sm;                      // [dim][query]
    float (*Ks)[QS_PITCH] = (float(*)[QS_PITCH])(sm + 64 * QS_PITCH);    // [dim][key]
    float (*Ps)[QS_PITCH] = (float(*)[QS_PITCH])(sm + 2 * 64 * QS_PITCH);// [key][query]
    float (*Vs)[64]       = (float(*)[64])      (sm + 3 * 64 * QS_PITCH);// [key][dim]

    int qt  = gridDim.x - 1 - blockIdx.x;   // heavy tiles first
    int h   = blockIdx.y;
    int kvh = h >> 2;
    int tid = threadIdx.x;
    int tr = tid >> 4, tc = tid & 15;
    int q0 = qt * 64;

    // load Q tile transposed: Qs[d][qi]
    #pragma unroll
    for (int t = 0; t < 4; t++) {
        int idx = tid + t * 256;
        int qi = idx >> 4;
        int d4 = (idx & 15) << 2;
        float4 v4 = *(const float4*)(Q + (size_t)(q0 + qi) * DMODEL + h * HDIM + d4);
        Qs[d4 + 0][qi] = v4.x; Qs[d4 + 1][qi] = v4.y;
        Qs[d4 + 2][qi] = v4.z; Qs[d4 + 3][qi] = v4.w;
    }

    float m[4], l[4], o[4][4];
    #pragma unroll
    for (int i = 0; i < 4; i++) {
        m[i] = -60.0f; l[i] = 0.0f;
        #pragma unroll
        for (int j = 0; j < 4; j++) o[i][j] = 0.0f;
    }

    int jt0 = 0;
    if (win > 0) { jt0 = qt - 4; if (jt0 < 0) jt0 = 0; }

    __syncthreads();

    for (int jt = jt0; jt <= qt; jt++) {
        int j0 = jt * 64;
        // load K tile transposed Ks[d][j], V tile natural Vs[j][d]
        #pragma unroll
        for (int t = 0; t < 4; t++) {
            int idx = tid + t * 256;
            int jj = idx >> 4;
            int d4 = (idx & 15) << 2;
            size_t base = (size_t)(j0 + jj) * LATD + kvh * HDIM + d4;
            float4 kv = *(const float4*)(K + base);
            Ks[d4 + 0][jj] = kv.x; Ks[d4 + 1][jj] = kv.y;
            Ks[d4 + 2][jj] = kv.z; Ks[d4 + 3][jj] = kv.w;
            *(float4*)&Vs[jj][d4] = *(const float4*)(V + base);
        }
        __syncthreads();

        // S = Q K^T
        float s[4][4];
        #pragma unroll
        for (int i = 0; i < 4; i++)
            #pragma unroll
            for (int j = 0; j < 4; j++) s[i][j] = 0.0f;
        #pragma unroll 8
        for (int kk = 0; kk < 64; kk++) {
            float4 qv = *(const float4*)&Qs[kk][tr << 2];
            float4 kv = *(const float4*)&Ks[kk][tc << 2];
            float a[4] = {qv.x, qv.y, qv.z, qv.w};
            float b[4] = {kv.x, kv.y, kv.z, kv.w};
            #pragma unroll
            for (int i = 0; i < 4; i++)
                #pragma unroll
                for (int j = 0; j < 4; j++)
                    s[i][j] += a[i] * b[j];
        }

        // scale + mask
        #pragma unroll
        for (int i = 0; i < 4; i++) {
            int q = q0 + (tr << 2) + i;
            #pragma unroll
            for (int j = 0; j < 4; j++) {
                int kj = j0 + (tc << 2) + j;
                float val = s[i][j] * 0.125f;
                bool vis = (kj <= q) && (win == 0 || (q - kj) < win);
                s[i][j] = vis ? val : -1e30f;
            }
        }

        // online softmax (row groups = 16 consecutive lanes, same warp)
        #pragma unroll
        for (int i = 0; i < 4; i++) {
            float rm = fmaxf(fmaxf(s[i][0], s[i][1]), fmaxf(s[i][2], s[i][3]));
            #pragma unroll
            for (int off = 8; off > 0; off >>= 1)
                rm = fmaxf(rm, __shfl_xor_sync(0xffffffffu, rm, off));
            float mn = fmaxf(m[i], rm);
            float alpha = __expf(m[i] - mn);
            float rs = 0.0f;
            #pragma unroll
            for (int j = 0; j < 4; j++) {
                float p = __expf(s[i][j] - mn);
                s[i][j] = p;
                rs += p;
            }
            #pragma unroll
            for (int off = 8; off > 0; off >>= 1)
                rs += __shfl_xor_sync(0xffffffffu, rs, off);
            l[i] = l[i] * alpha + rs;
            m[i] = mn;
            #pragma unroll
            for (int j = 0; j < 4; j++) o[i][j] *= alpha;
        }

        // store P transposed: Ps[key][query] (same-warp producer/consumer)
        #pragma unroll
        for (int j = 0; j < 4; j++) {
            float4 pv = make_float4(s[0][j], s[1][j], s[2][j], s[3][j]);
            *(float4*)&Ps[(tc << 2) + j][tr << 2] = pv;
        }
        __syncwarp();

        // O += P^T V
        #pragma unroll 8
        for (int kk = 0; kk < 64; kk++) {
            float4 pv = *(const float4*)&Ps[kk][tr << 2];
            float4 vv = *(const float4*)&Vs[kk][tc << 2];
            float a[4] = {pv.x, pv.y, pv.z, pv.w};
            float b[4] = {vv.x, vv.y, vv.z, vv.w};
            #pragma unroll
            for (int i = 0; i < 4; i++)
                #pragma unroll
                for (int j = 0; j < 4; j++)
                    o[i][j] += a[i] * b[j];
        }
        __syncthreads();
    }

    #pragma unroll
    for (int i = 0; i < 4; i++) {
        float invl = 1.0f / l[i];
        int q = q0 + (tr << 2) + i;
        float4 ov = make_float4(o[i][0] * invl, o[i][1] * invl,
                                o[i][2] * invl, o[i][3] * invl);
        *(float4*)(O + (size_t)q * DMODEL + h * HDIM + (tc << 2)) = ov;
    }
}

// ---------------------------------------------------------------------------
// Launch
// ---------------------------------------------------------------------------
extern "C" void kernel_launch(void* const* d_in, const int* in_sizes, int n_in,
                              void* d_out, int out_size) {
    (void)in_sizes; (void)n_in; (void)out_size;

    const float* hidden   = (const float*)d_in[0];
    const float* norm1_w  = (const float*)d_in[1];
    const float* norm2_w  = (const float*)d_in[2];
    const float* w_g_wq   = (const float*)d_in[3];
    const float* w_g_kvdn = (const float*)d_in[4];
    const float* w_g_k_up = (const float*)d_in[5];
    const float* w_g_v_up = (const float*)d_in[6];
    const float* w_g_wo   = (const float*)d_in[7];
    const float* w_l_wq   = (const float*)d_in[8];
    const float* w_l_wk   = (const float*)d_in[9];
    const float* w_l_wv   = (const float*)d_in[10];
    const float* w_l_wo   = (const float*)d_in[11];
    float* out = (float*)d_out;

    float *x1, *q, *lat, *k, *v, *attn;
    cudaGetSymbolAddress((void**)&x1,   g_x1);
    cudaGetSymbolAddress((void**)&q,    g_q);
    cudaGetSymbolAddress((void**)&lat,  g_lat);
    cudaGetSymbolAddress((void**)&k,    g_k);
    cudaGetSymbolAddress((void**)&v,    g_v);
    cudaGetSymbolAddress((void**)&attn, g_attn);

    const int ATTN_SMEM = (3 * 64 * QS_PITCH + 64 * 64) * sizeof(float); // 68608
    cudaFuncSetAttribute(fattn_kernel,
                         cudaFuncAttributeMaxDynamicSharedMemorySize, ATTN_SMEM);

    dim3 gridBig(DMODEL / 128, SEQ / 128);   // (8, 16)
    dim3 gridSm (LATD  / 64,  SEQ / 64);     // (4, 32)
    dim3 gridAttn(SEQ / 64, NH);             // (32, 16)

    // ---- Layer 1: global latent attention ----
    rmsnorm_kernel<<<SEQ, 256>>>(hidden, norm1_w, x1);
    sgemm_tpl<128,128><<<gridBig, 256>>>(x1,  w_g_wq,   nullptr, q,   DMODEL, DMODEL);
    sgemm_tpl<64,64>  <<<gridSm,  256>>>(x1,  w_g_kvdn, nullptr, lat, LATD,   DMODEL);
    sgemm_tpl<64,64>  <<<gridSm,  256>>>(lat, w_g_k_up, nullptr, k,   LATD,   LATD);
    sgemm_tpl<64,64>  <<<gridSm,  256>>>(lat, w_g_v_up, nullptr, v,   LATD,   LATD);
    rope_qknorm_kernel<<<dim3(SEQ, NH),   32>>>(q, NH,   1000000.0f);
    rope_qknorm_kernel<<<dim3(SEQ, NKVH), 32>>>(k, NKVH, 1000000.0f);
    fattn_kernel<<<gridAttn, 256, ATTN_SMEM>>>(q, k, v, attn, /*win=*/0);
    sgemm_tpl<128,128><<<gridBig, 256>>>(attn, w_g_wo, hidden, out, DMODEL, DMODEL);

    // ---- Layer 2: local GQA attention ----
    rmsnorm_kernel<<<SEQ, 256>>>(out, norm2_w, x1);
    sgemm_tpl<128,128><<<gridBig, 256>>>(x1, w_l_wq, nullptr, q, DMODEL, DMODEL);
    sgemm_tpl<64,64>  <<<gridSm,  256>>>(x1, w_l_wk, nullptr, k, LATD, DMODEL);
    sgemm_tpl<64,64>  <<<gridSm,  256>>>(x1, w_l_wv, nullptr, v, LATD, DMODEL);
    rope_qknorm_kernel<<<dim3(SEQ, NH),   32>>>(q, NH,   10000.0f);
    rope_qknorm_kernel<<<dim3(SEQ, NKVH), 32>>>(k, NKVH, 10000.0f);
    fattn_kernel<<<gridAttn, 256, ATTN_SMEM>>>(q, k, v, attn, /*win=*/WINSZ);
    sgemm_tpl<128,128><<<gridBig, 256>>>(attn, w_l_wo, out, out, DMODEL, DMODEL);
}

// round 7
// speedup vs baseline: 4.7745x; 1.2625x over previous
#include <cuda_runtime.h>
#include <math.h>
#include <stdint.h>

#define SEQ    2048
#define DMODEL 1024
#define NH     16
#define NKVH   4
#define HDIM   64
#define LATD   256
#define WINSZ  256

// ---------------------------------------------------------------------------
// Scratch (device globals; no allocation allowed)
// ---------------------------------------------------------------------------
__device__ float g_x1  [SEQ * DMODEL];
__device__ float g_q   [SEQ * DMODEL];
__device__ float g_lat [SEQ * LATD];
__device__ float g_k   [SEQ * LATD];
__device__ float g_v   [SEQ * LATD];
__device__ float g_attn[SEQ * DMODEL];

// ---------------------------------------------------------------------------
// Helpers
// ---------------------------------------------------------------------------
__device__ __forceinline__ uint32_t f2tf32(float x) {
    uint32_t u;
    asm("cvt.rna.tf32.f32 %0, %1;" : "=r"(u) : "f"(x));
    return u;
}

__device__ __forceinline__ void mma_tf32(float* c,
                                         uint32_t a0, uint32_t a1,
                                         uint32_t a2, uint32_t a3,
                                         uint32_t b0, uint32_t b1) {
    asm volatile(
        "mma.sync.aligned.m16n8k8.row.col.f32.tf32.tf32.f32 "
        "{%0,%1,%2,%3}, {%4,%5,%6,%7}, {%8,%9}, {%0,%1,%2,%3};\n"
        : "+f"(c[0]), "+f"(c[1]), "+f"(c[2]), "+f"(c[3])
        : "r"(a0), "r"(a1), "r"(a2), "r"(a3), "r"(b0), "r"(b1));
}

// ---------------------------------------------------------------------------
// RMSNorm: one block per row, 256 threads, float4 per thread (D=1024)
// ---------------------------------------------------------------------------
__global__ void rmsnorm_kernel(const float* __restrict__ x,
                               const float* __restrict__ w,
                               float* __restrict__ y) {
    int row = blockIdx.x;
    int tid = threadIdx.x;
    const float4* xr = (const float4*)(x + (size_t)row * DMODEL);
    float4 v = xr[tid];
    float ss = v.x * v.x + v.y * v.y + v.z * v.z + v.w * v.w;
    __shared__ float red[256];
    red[tid] = ss;
    __syncthreads();
    #pragma unroll
    for (int o = 128; o > 0; o >>= 1) {
        if (tid < o) red[tid] += red[tid + o];
        __syncthreads();
    }
    float r = rsqrtf(red[0] / (float)DMODEL + 1e-6f);
    float4 wv = ((const float4*)w)[tid];
    float4 o4 = make_float4(v.x * r * wv.x, v.y * r * wv.y,
                            v.z * r * wv.z, v.w * r * wv.w);
    ((float4*)(y + (size_t)row * DMODEL))[tid] = o4;
}

// ---------------------------------------------------------------------------
// TF32 tensor-core GEMM: C[M,N] = A[M,K] @ B[K,N] (+ R if non-null)
// BMxBN tile, BK=16 double-buffered, 256 threads = 8 warps (4 m x 2 n).
// mma.sync m16n8k8 tf32. Inputs rounded to tf32 once at SMEM store.
// Requires M%BM==0, N%BN==0, K%16==0.
// ---------------------------------------------------------------------------
template<int BM, int BN>
__global__ __launch_bounds__(256)
void mma_gemm(const float* __restrict__ A, const float* __restrict__ B,
              const float* __restrict__ R, float* __restrict__ C,
              int N, int K) {
    constexpr int AP  = BM + 8;         // As pitch (floats): bank-conflict-free frags
    constexpr int BP  = BN + 8;         // Bs pitch
    constexpr int WM  = BM / 4;         // warp tile m (4 warps in m)
    constexpr int WN  = BN / 2;         // warp tile n (2 warps in n)
    constexpr int MT  = WM / 16;        // m16 tiles per warp
    constexpr int NT  = WN / 8;         // n8 tiles per warp
    constexpr int ALD = BM / 64;        // float4 A-loads per thread per k-block
    constexpr int BLD = BN / 64;        // float4 B-loads per thread per k-block
    constexpr int BF4 = BN / 4;

    __shared__ __align__(16) float As[2][16][AP];   // [k][m], tf32-rounded
    __shared__ __align__(16) float Bs[2][16][BP];   // [k][n], tf32-rounded

    int tid  = threadIdx.x;
    int wid  = tid >> 5;
    int lane = tid & 31;
    int g    = lane >> 2;      // 0..7
    int cq   = lane & 3;       // 0..3
    int wm   = (wid >> 1) * WM;
    int wn   = (wid & 1) * WN;
    int r0   = blockIdx.y * BM;
    int c0   = blockIdx.x * BN;

    float acc[MT][NT][4];
    #pragma unroll
    for (int t = 0; t < MT; t++)
        #pragma unroll
        for (int u = 0; u < NT; u++)
            #pragma unroll
            for (int i = 0; i < 4; i++) acc[t][u][i] = 0.0f;

    // ---- prologue: stage k-block 0 into buffer 0 ----
    #pragma unroll
    for (int t = 0; t < ALD; t++) {
        int idx = tid + t * 256;
        int arow = idx >> 2;
        int ac4  = (idx & 3) << 2;
        float4 a = *(const float4*)(A + (size_t)(r0 + arow) * K + ac4);
        As[0][ac4 + 0][arow] = __uint_as_float(f2tf32(a.x));
        As[0][ac4 + 1][arow] = __uint_as_float(f2tf32(a.y));
        As[0][ac4 + 2][arow] = __uint_as_float(f2tf32(a.z));
        As[0][ac4 + 3][arow] = __uint_as_float(f2tf32(a.w));
    }
    #pragma unroll
    for (int t = 0; t < BLD; t++) {
        int idx = tid + t * 256;
        int brow = idx / BF4;
        int bcol = (idx % BF4) * 4;
        float4 b = *(const float4*)(B + (size_t)brow * N + c0 + bcol);
        uint4 ub = make_uint4(f2tf32(b.x), f2tf32(b.y), f2tf32(b.z), f2tf32(b.w));
        *(uint4*)&Bs[0][brow][bcol] = ub;
    }
    __syncthreads();

    int NKB = K >> 4;
    int cur = 0;
    for (int kb = 0; kb < NKB; kb++) {
        float4 pa[ALD];
        float4 pb[BLD];
        bool more = (kb + 1 < NKB);
        int k0n = (kb + 1) << 4;
        if (more) {
            #pragma unroll
            for (int t = 0; t < ALD; t++) {
                int idx = tid + t * 256;
                int arow = idx >> 2;
                int ac4  = (idx & 3) << 2;
                pa[t] = *(const float4*)(A + (size_t)(r0 + arow) * K + k0n + ac4);
            }
            #pragma unroll
            for (int t = 0; t < BLD; t++) {
                int idx = tid + t * 256;
                int brow = idx / BF4;
                int bcol = (idx % BF4) * 4;
                pb[t] = *(const float4*)(B + (size_t)(k0n + brow) * N + c0 + bcol);
            }
        }

        // ---- compute on buffer cur ----
        #pragma unroll
        for (int k8 = 0; k8 < 16; k8 += 8) {
            uint32_t af[MT][4];
            #pragma unroll
            for (int t = 0; t < MT; t++) {
                int m0 = wm + 16 * t + g;
                af[t][0] = __float_as_uint(As[cur][k8 + cq    ][m0    ]);
                af[t][1] = __float_as_uint(As[cur][k8 + cq    ][m0 + 8]);
                af[t][2] = __float_as_uint(As[cur][k8 + cq + 4][m0    ]);
                af[t][3] = __float_as_uint(As[cur][k8 + cq + 4][m0 + 8]);
            }
            uint32_t bf[NT][2];
            #pragma unroll
            for (int u = 0; u < NT; u++) {
                int n0 = wn + 8 * u + g;
                bf[u][0] = __float_as_uint(Bs[cur][k8 + cq    ][n0]);
                bf[u][1] = __float_as_uint(Bs[cur][k8 + cq + 4][n0]);
            }
            #pragma unroll
            for (int t = 0; t < MT; t++)
                #pragma unroll
                for (int u = 0; u < NT; u++)
                    mma_tf32(acc[t][u], af[t][0], af[t][1], af[t][2], af[t][3],
                             bf[u][0], bf[u][1]);
        }

        if (more) {
            int nxt = cur ^ 1;
            #pragma unroll
            for (int t = 0; t < ALD; t++) {
                int idx = tid + t * 256;
                int arow = idx >> 2;
                int ac4  = (idx & 3) << 2;
                As[nxt][ac4 + 0][arow] = __uint_as_float(f2tf32(pa[t].x));
                As[nxt][ac4 + 1][arow] = __uint_as_float(f2tf32(pa[t].y));
                As[nxt][ac4 + 2][arow] = __uint_as_float(f2tf32(pa[t].z));
                As[nxt][ac4 + 3][arow] = __uint_as_float(f2tf32(pa[t].w));
            }
            #pragma unroll
            for (int t = 0; t < BLD; t++) {
                int idx = tid + t * 256;
                int brow = idx / BF4;
                int bcol = (idx % BF4) * 4;
                uint4 ub = make_uint4(f2tf32(pb[t].x), f2tf32(pb[t].y),
                                      f2tf32(pb[t].z), f2tf32(pb[t].w));
                *(uint4*)&Bs[nxt][brow][bcol] = ub;
            }
            __syncthreads();
            cur = nxt;
        }
    }

    // ---- epilogue: fragment layout c0:(g,2c) c1:(g,2c+1) c2:(g+8,..) ----
    #pragma unroll
    for (int t = 0; t < MT; t++) {
        int row = r0 + wm + 16 * t + g;
        #pragma unroll
        for (int u = 0; u < NT; u++) {
            int col = c0 + wn + 8 * u + 2 * cq;
            size_t off0 = (size_t)row * N + col;
            size_t off1 = (size_t)(row + 8) * N + col;
            float2 r0v = make_float2(0.f, 0.f), r1v = make_float2(0.f, 0.f);
            if (R) {
                r0v = *(const float2*)(R + off0);
                r1v = *(const float2*)(R + off1);
            }
            *(float2*)(C + off0) = make_float2(acc[t][u][0] + r0v.x,
                                               acc[t][u][1] + r0v.y);
            *(float2*)(C + off1) = make_float2(acc[t][u][2] + r1v.x,
                                               acc[t][u][3] + r1v.y);
        }
    }
}

// ---------------------------------------------------------------------------
// Fused RoPE + qk_norm (hd=64). Grid: (SEQ, nheads), 32 threads.
// ---------------------------------------------------------------------------
__global__ void rope_qknorm_kernel(float* __restrict__ x, int nheads, float base) {
    int s = blockIdx.x;
    int h = blockIdx.y;
    int i = threadIdx.x;
    float* p = x + (size_t)s * nheads * HDIM + h * HDIM;

    float invf = powf(base, -((float)(2 * i) / (float)HDIM));
    float ang = (float)s * invf;
    float sn, cs;
    sincosf(ang, &sn, &cs);

    float xe = p[2 * i];
    float xo = p[2 * i + 1];
    float re = xe * cs - xo * sn;
    float ro = xe * sn + xo * cs;

    float ss = re * re + ro * ro;
    #pragma unroll
    for (int o = 16; o > 0; o >>= 1)
        ss += __shfl_xor_sync(0xffffffffu, ss, o);

    float r = rsqrtf(ss / (float)HDIM + 1e-6f);
    p[2 * i]     = re * r;
    p[2 * i + 1] = ro * r;
}

// ---------------------------------------------------------------------------
// Flash-style attention: block per (64-query tile, head). 256 threads.
// Online softmax, K/V tiles of 64 streamed through SMEM. fp32.
// ---------------------------------------------------------------------------
#define QS_PITCH 68
__global__ __launch_bounds__(256, 1)
void fattn_kernel(const float* __restrict__ Q, const float* __restrict__ K,
                  const float* __restrict__ V, float* __restrict__ O,
                  int win) {
    extern __shared__ float sm[];
    float (*Qs)[QS_PITCH] = (float(*)[QS_PITCH])sm;
    float (*Ks)[QS_PITCH] = (float(*)[QS_PITCH])(sm + 64 * QS_PITCH);
    float (*Ps)[QS_PITCH] = (float(*)[QS_PITCH])(sm + 2 * 64 * QS_PITCH);
    float (*Vs)[64]       = (float(*)[64])      (sm + 3 * 64 * QS_PITCH);

    int qt  = gridDim.x - 1 - blockIdx.x;
    int h   = blockIdx.y;
    int kvh = h >> 2;
    int tid = threadIdx.x;
    int tr = tid >> 4, tc = tid & 15;
    int q0 = qt * 64;

    #pragma unroll
    for (int t = 0; t < 4; t++) {
        int idx = tid + t * 256;
        int qi = idx >> 4;
        int d4 = (idx & 15) << 2;
        float4 v4 = *(const float4*)(Q + (size_t)(q0 + qi) * DMODEL + h * HDIM + d4);
        Qs[d4 + 0][qi] = v4.x; Qs[d4 + 1][qi] = v4.y;
        Qs[d4 + 2][qi] = v4.z; Qs[d4 + 3][qi] = v4.w;
    }

    float m[4], l[4], o[4][4];
    #pragma unroll
    for (int i = 0; i < 4; i++) {
        m[i] = -60.0f; l[i] = 0.0f;
        #pragma unroll
        for (int j = 0; j < 4; j++) o[i][j] = 0.0f;
    }

    int jt0 = 0;
    if (win > 0) { jt0 = qt - 4; if (jt0 < 0) jt0 = 0; }

    __syncthreads();

    for (int jt = jt0; jt <= qt; jt++) {
        int j0 = jt * 64;
        #pragma unroll
        for (int t = 0; t < 4; t++) {
            int idx = tid + t * 256;
            int jj = idx >> 4;
            int d4 = (idx & 15) << 2;
            size_t base = (size_t)(j0 + jj) * LATD + kvh * HDIM + d4;
            float4 kv = *(const float4*)(K + base);
            Ks[d4 + 0][jj] = kv.x; Ks[d4 + 1][jj] = kv.y;
            Ks[d4 + 2][jj] = kv.z; Ks[d4 + 3][jj] = kv.w;
            *(float4*)&Vs[jj][d4] = *(const float4*)(V + base);
        }
        __syncthreads();

        float s[4][4];
        #pragma unroll
        for (int i = 0; i < 4; i++)
            #pragma unroll
            for (int j = 0; j < 4; j++) s[i][j] = 0.0f;
        #pragma unroll 8
        for (int kk = 0; kk < 64; kk++) {
            float4 qv = *(const float4*)&Qs[kk][tr << 2];
            float4 kv = *(const float4*)&Ks[kk][tc << 2];
            float a[4] = {qv.x, qv.y, qv.z, qv.w};
            float b[4] = {kv.x, kv.y, kv.z, kv.w};
            #pragma unroll
            for (int i = 0; i < 4; i++)
                #pragma unroll
                for (int j = 0; j < 4; j++)
                    s[i][j] += a[i] * b[j];
        }

        #pragma unroll
        for (int i = 0; i < 4; i++) {
            int q = q0 + (tr << 2) + i;
            #pragma unroll
            for (int j = 0; j < 4; j++) {
                int kj = j0 + (tc << 2) + j;
                float val = s[i][j] * 0.125f;
                bool vis = (kj <= q) && (win == 0 || (q - kj) < win);
                s[i][j] = vis ? val : -1e30f;
            }
        }

        #pragma unroll
        for (int i = 0; i < 4; i++) {
            float rm = fmaxf(fmaxf(s[i][0], s[i][1]), fmaxf(s[i][2], s[i][3]));
            #pragma unroll
            for (int off = 8; off > 0; off >>= 1)
                rm = fmaxf(rm, __shfl_xor_sync(0xffffffffu, rm, off));
            float mn = fmaxf(m[i], rm);
            float alpha = __expf(m[i] - mn);
            float rs = 0.0f;
            #pragma unroll
            for (int j = 0; j < 4; j++) {
                float p = __expf(s[i][j] - mn);
                s[i][j] = p;
                rs += p;
            }
            #pragma unroll
            for (int off = 8; off > 0; off >>= 1)
                rs += __shfl_xor_sync(0xffffffffu, rs, off);
            l[i] = l[i] * alpha + rs;
            m[i] = mn;
            #pragma unroll
            for (int j = 0; j < 4; j++) o[i][j] *= alpha;
        }

        #pragma unroll
        for (int j = 0; j < 4; j++) {
            float4 pv = make_float4(s[0][j], s[1][j], s[2][j], s[3][j]);
            *(float4*)&Ps[(tc << 2) + j][tr << 2] = pv;
        }
        __syncwarp();

        #pragma unroll 8
        for (int kk = 0; kk < 64; kk++) {
            float4 pv = *(const float4*)&Ps[kk][tr << 2];
            float4 vv = *(const float4*)&Vs[kk][tc << 2];
            float a[4] = {pv.x, pv.y, pv.z, pv.w};
            float b[4] = {vv.x, vv.y, vv.z, vv.w};
            #pragma unroll
            for (int i = 0; i < 4; i++)
                #pragma unroll
                for (int j = 0; j < 4; j++)
                    o[i][j] += a[i] * b[j];
        }
        __syncthreads();
    }

    #pragma unroll
    for (int i = 0; i < 4; i++) {
        float invl = 1.0f / l[i];
        int q = q0 + (tr << 2) + i;
        float4 ov = make_float4(o[i][0] * invl, o[i][1] * invl,
                                o[i][2] * invl, o[i][3] * invl);
        *(float4*)(O + (size_t)q * DMODEL + h * HDIM + (tc << 2)) = ov;
    }
}

// ---------------------------------------------------------------------------
// Launch
// ---------------------------------------------------------------------------
extern "C" void kernel_launch(void* const* d_in, const int* in_sizes, int n_in,
                              void* d_out, int out_size) {
    (void)in_sizes; (void)n_in; (void)out_size;

    const float* hidden   = (const float*)d_in[0];
    const float* norm1_w  = (const float*)d_in[1];
    const float* norm2_w  = (const float*)d_in[2];
    const float* w_g_wq   = (const float*)d_in[3];
    const float* w_g_kvdn = (const float*)d_in[4];
    const float* w_g_k_up = (const float*)d_in[5];
    const float* w_g_v_up = (const float*)d_in[6];
    const float* w_g_wo   = (const float*)d_in[7];
    const float* w_l_wq   = (const float*)d_in[8];
    const float* w_l_wk   = (const float*)d_in[9];
    const float* w_l_wv   = (const float*)d_in[10];
    const float* w_l_wo   = (const float*)d_in[11];
    float* out = (float*)d_out;

    float *x1, *q, *lat, *k, *v, *attn;
    cudaGetSymbolAddress((void**)&x1,   g_x1);
    cudaGetSymbolAddress((void**)&q,    g_q);
    cudaGetSymbolAddress((void**)&lat,  g_lat);
    cudaGetSymbolAddress((void**)&k,    g_k);
    cudaGetSymbolAddress((void**)&v,    g_v);
    cudaGetSymbolAddress((void**)&attn, g_attn);

    const int ATTN_SMEM = (3 * 64 * QS_PITCH + 64 * 64) * sizeof(float);
    cudaFuncSetAttribute(fattn_kernel,
                         cudaFuncAttributeMaxDynamicSharedMemorySize, ATTN_SMEM);

    dim3 gridBig(DMODEL / 128, SEQ / 128);   // (8, 16)
    dim3 gridSm (LATD  / 64,  SEQ / 64);     // (4, 32)
    dim3 gridAttn(SEQ / 64, NH);             // (32, 16)

    // ---- Layer 1: global latent attention ----
    rmsnorm_kernel<<<SEQ, 256>>>(hidden, norm1_w, x1);
    mma_gemm<128,128><<<gridBig, 256>>>(x1,  w_g_wq,   nullptr, q,   DMODEL, DMODEL);
    mma_gemm<64,64>  <<<gridSm,  256>>>(x1,  w_g_kvdn, nullptr, lat, LATD,   DMODEL);
    mma_gemm<64,64>  <<<gridSm,  256>>>(lat, w_g_k_up, nullptr, k,   LATD,   LATD);
    mma_gemm<64,64>  <<<gridSm,  256>>>(lat, w_g_v_up, nullptr, v,   LATD,   LATD);
    rope_qknorm_kernel<<<dim3(SEQ, NH),   32>>>(q, NH,   1000000.0f);
    rope_qknorm_kernel<<<dim3(SEQ, NKVH), 32>>>(k, NKVH, 1000000.0f);
    fattn_kernel<<<gridAttn, 256, ATTN_SMEM>>>(q, k, v, attn, /*win=*/0);
    mma_gemm<128,128><<<gridBig, 256>>>(attn, w_g_wo, hidden, out, DMODEL, DMODEL);

    // ---- Layer 2: local GQA attention ----
    rmsnorm_kernel<<<SEQ, 256>>>(out, norm2_w, x1);
    mma_gemm<128,128><<<gridBig, 256>>>(x1, w_l_wq, nullptr, q, DMODEL, DMODEL);
    mma_gemm<64,64>  <<<gridSm,  256>>>(x1, w_l_wk, nullptr, k, LATD, DMODEL);
    mma_gemm<64,64>  <<<gridSm,  256>>>(x1, w_l_wv, nullptr, v, LATD, DMODEL);
    rope_qknorm_kernel<<<dim3(SEQ, NH),   32>>>(q, NH,   10000.0f);
    rope_qknorm_kernel<<<dim3(SEQ, NKVH), 32>>>(k, NKVH, 10000.0f);
    fattn_kernel<<<gridAttn, 256, ATTN_SMEM>>>(q, k, v, attn, /*win=*/WINSZ);
    mma_gemm<128,128><<<gridBig, 256>>>(attn, w_l_wo, out, out, DMODEL, DMODEL);
}

// round 8
// speedup vs baseline: 7.1964x; 1.5073x over previous
#include <cuda_runtime.h>
#include <math.h>
#include <stdint.h>

#define SEQ    2048
#define DMODEL 1024
#define NH     16
#define NKVH   4
#define HDIM   64
#define LATD   256
#define WINSZ  256

// ---------------------------------------------------------------------------
// Scratch (device globals; no allocation allowed)
// ---------------------------------------------------------------------------
__device__ float g_x1  [SEQ * DMODEL];
__device__ float g_q   [SEQ * DMODEL];
__device__ float g_lat [SEQ * LATD];
__device__ float g_k   [SEQ * LATD];
__device__ float g_v   [SEQ * LATD];
__device__ float g_attn[SEQ * DMODEL];

// ---------------------------------------------------------------------------
// Helpers
// ---------------------------------------------------------------------------
__device__ __forceinline__ uint32_t f2tf32(float x) {
    uint32_t u;
    asm("cvt.rna.tf32.f32 %0, %1;" : "=r"(u) : "f"(x));
    return u;
}

__device__ __forceinline__ void mma_tf32(float* c,
                                         uint32_t a0, uint32_t a1,
                                         uint32_t a2, uint32_t a3,
                                         uint32_t b0, uint32_t b1) {
    asm volatile(
        "mma.sync.aligned.m16n8k8.row.col.f32.tf32.tf32.f32 "
        "{%0,%1,%2,%3}, {%4,%5,%6,%7}, {%8,%9}, {%0,%1,%2,%3};\n"
        : "+f"(c[0]), "+f"(c[1]), "+f"(c[2]), "+f"(c[3])
        : "r"(a0), "r"(a1), "r"(a2), "r"(a3), "r"(b0), "r"(b1));
}

// ---------------------------------------------------------------------------
// RMSNorm
// ---------------------------------------------------------------------------
__global__ void rmsnorm_kernel(const float* __restrict__ x,
                               const float* __restrict__ w,
                               float* __restrict__ y) {
    int row = blockIdx.x;
    int tid = threadIdx.x;
    const float4* xr = (const float4*)(x + (size_t)row * DMODEL);
    float4 v = xr[tid];
    float ss = v.x * v.x + v.y * v.y + v.z * v.z + v.w * v.w;
    __shared__ float red[256];
    red[tid] = ss;
    __syncthreads();
    #pragma unroll
    for (int o = 128; o > 0; o >>= 1) {
        if (tid < o) red[tid] += red[tid + o];
        __syncthreads();
    }
    float r = rsqrtf(red[0] / (float)DMODEL + 1e-6f);
    float4 wv = ((const float4*)w)[tid];
    float4 o4 = make_float4(v.x * r * wv.x, v.y * r * wv.y,
                            v.z * r * wv.z, v.w * r * wv.w);
    ((float4*)(y + (size_t)row * DMODEL))[tid] = o4;
}

// ---------------------------------------------------------------------------
// TF32 tensor-core GEMM: C = A @ B (+ R). BMxBNxBK tiles, double-buffered.
// 256 threads = 8 warps (4 m x 2 n).
// ---------------------------------------------------------------------------
template<int BM, int BN, int BK>
__global__ __launch_bounds__(256)
void mma_gemm(const float* __restrict__ A, const float* __restrict__ B,
              const float* __restrict__ R, float* __restrict__ C,
              int N, int K) {
    constexpr int AP  = BM + 4;
    constexpr int BP  = BN + 8;
    constexpr int WM  = BM / 4;
    constexpr int WN  = BN / 2;
    constexpr int MT  = WM / 16;
    constexpr int NT  = WN / 8;
    constexpr int ALD = BM * BK / 1024;   // float4 A-loads/thread
    constexpr int BLD = BK * BN / 1024;   // float4 B-loads/thread
    constexpr int AK4 = BK / 4;
    constexpr int BF4 = BN / 4;

    __shared__ __align__(16) float As[2][BK][AP];   // [k][m]
    __shared__ __align__(16) float Bs[2][BK][BP];   // [k][n]

    int tid  = threadIdx.x;
    int wid  = tid >> 5;
    int lane = tid & 31;
    int g    = lane >> 2;
    int cq   = lane & 3;
    int wm   = (wid >> 1) * WM;
    int wn   = (wid & 1) * WN;
    int r0   = blockIdx.y * BM;
    int c0   = blockIdx.x * BN;

    float acc[MT][NT][4];
    #pragma unroll
    for (int t = 0; t < MT; t++)
        #pragma unroll
        for (int u = 0; u < NT; u++)
            #pragma unroll
            for (int i = 0; i < 4; i++) acc[t][u][i] = 0.0f;

    #pragma unroll
    for (int t = 0; t < ALD; t++) {
        int idx = tid + t * 256;
        int arow = idx / AK4;
        int ak4  = (idx % AK4) << 2;
        float4 a = *(const float4*)(A + (size_t)(r0 + arow) * K + ak4);
        As[0][ak4 + 0][arow] = __uint_as_float(f2tf32(a.x));
        As[0][ak4 + 1][arow] = __uint_as_float(f2tf32(a.y));
        As[0][ak4 + 2][arow] = __uint_as_float(f2tf32(a.z));
        As[0][ak4 + 3][arow] = __uint_as_float(f2tf32(a.w));
    }
    #pragma unroll
    for (int t = 0; t < BLD; t++) {
        int idx = tid + t * 256;
        int brow = idx / BF4;
        int bcol = (idx % BF4) * 4;
        float4 b = *(const float4*)(B + (size_t)brow * N + c0 + bcol);
        uint4 ub = make_uint4(f2tf32(b.x), f2tf32(b.y), f2tf32(b.z), f2tf32(b.w));
        *(uint4*)&Bs[0][brow][bcol] = ub;
    }
    __syncthreads();

    int NKB = K / BK;
    int cur = 0;
    for (int kb = 0; kb < NKB; kb++) {
        float4 pa[ALD];
        float4 pb[BLD];
        bool more = (kb + 1 < NKB);
        int k0n = (kb + 1) * BK;
        if (more) {
            #pragma unroll
            for (int t = 0; t < ALD; t++) {
                int idx = tid + t * 256;
                int arow = idx / AK4;
                int ak4  = (idx % AK4) << 2;
                pa[t] = *(const float4*)(A + (size_t)(r0 + arow) * K + k0n + ak4);
            }
            #pragma unroll
            for (int t = 0; t < BLD; t++) {
                int idx = tid + t * 256;
                int brow = idx / BF4;
                int bcol = (idx % BF4) * 4;
                pb[t] = *(const float4*)(B + (size_t)(k0n + brow) * N + c0 + bcol);
            }
        }

        #pragma unroll
        for (int k8 = 0; k8 < BK; k8 += 8) {
            uint32_t af[MT][4];
            #pragma unroll
            for (int t = 0; t < MT; t++) {
                int m0 = wm + 16 * t + g;
                af[t][0] = __float_as_uint(As[cur][k8 + cq    ][m0    ]);
                af[t][1] = __float_as_uint(As[cur][k8 + cq    ][m0 + 8]);
                af[t][2] = __float_as_uint(As[cur][k8 + cq + 4][m0    ]);
                af[t][3] = __float_as_uint(As[cur][k8 + cq + 4][m0 + 8]);
            }
            uint32_t bf[NT][2];
            #pragma unroll
            for (int u = 0; u < NT; u++) {
                int n0 = wn + 8 * u + g;
                bf[u][0] = __float_as_uint(Bs[cur][k8 + cq    ][n0]);
                bf[u][1] = __float_as_uint(Bs[cur][k8 + cq + 4][n0]);
            }
            #pragma unroll
            for (int t = 0; t < MT; t++)
                #pragma unroll
                for (int u = 0; u < NT; u++)
                    mma_tf32(acc[t][u], af[t][0], af[t][1], af[t][2], af[t][3],
                             bf[u][0], bf[u][1]);
        }

        if (more) {
            int nxt = cur ^ 1;
            #pragma unroll
            for (int t = 0; t < ALD; t++) {
                int idx = tid + t * 256;
                int arow = idx / AK4;
                int ak4  = (idx % AK4) << 2;
                As[nxt][ak4 + 0][arow] = __uint_as_float(f2tf32(pa[t].x));
                As[nxt][ak4 + 1][arow] = __uint_as_float(f2tf32(pa[t].y));
                As[nxt][ak4 + 2][arow] = __uint_as_float(f2tf32(pa[t].z));
                As[nxt][ak4 + 3][arow] = __uint_as_float(f2tf32(pa[t].w));
            }
            #pragma unroll
            for (int t = 0; t < BLD; t++) {
                int idx = tid + t * 256;
                int brow = idx / BF4;
                int bcol = (idx % BF4) * 4;
                uint4 ub = make_uint4(f2tf32(pb[t].x), f2tf32(pb[t].y),
                                      f2tf32(pb[t].z), f2tf32(pb[t].w));
                *(uint4*)&Bs[nxt][brow][bcol] = ub;
            }
            __syncthreads();
            cur = nxt;
        }
    }

    #pragma unroll
    for (int t = 0; t < MT; t++) {
        int row = r0 + wm + 16 * t + g;
        #pragma unroll
        for (int u = 0; u < NT; u++) {
            int col = c0 + wn + 8 * u + 2 * cq;
            size_t off0 = (size_t)row * N + col;
            size_t off1 = (size_t)(row + 8) * N + col;
            float2 r0v = make_float2(0.f, 0.f), r1v = make_float2(0.f, 0.f);
            if (R) {
                r0v = *(const float2*)(R + off0);
                r1v = *(const float2*)(R + off1);
            }
            *(float2*)(C + off0) = make_float2(acc[t][u][0] + r0v.x,
                                               acc[t][u][1] + r0v.y);
            *(float2*)(C + off1) = make_float2(acc[t][u][2] + r1v.x,
                                               acc[t][u][3] + r1v.y);
        }
    }
}

// ---------------------------------------------------------------------------
// Fused RoPE + qk_norm (hd=64). Grid: (SEQ, nheads), 32 threads.
// ---------------------------------------------------------------------------
__global__ void rope_qknorm_kernel(float* __restrict__ x, int nheads, float base) {
    int s = blockIdx.x;
    int h = blockIdx.y;
    int i = threadIdx.x;
    float* p = x + (size_t)s * nheads * HDIM + h * HDIM;

    float invf = powf(base, -((float)(2 * i) / (float)HDIM));
    float ang = (float)s * invf;
    float sn, cs;
    sincosf(ang, &sn, &cs);

    float xe = p[2 * i];
    float xo = p[2 * i + 1];
    float re = xe * cs - xo * sn;
    float ro = xe * sn + xo * cs;

    float ss = re * re + ro * ro;
    #pragma unroll
    for (int o = 16; o > 0; o >>= 1)
        ss += __shfl_xor_sync(0xffffffffu, ss, o);

    float r = rsqrtf(ss / (float)HDIM + 1e-6f);
    p[2 * i]     = re * r;
    p[2 * i + 1] = ro * r;
}

// ---------------------------------------------------------------------------
// TF32 mma flash attention. Block = (64-query tile, head), 128 threads/4 warps.
// Warp w owns q-rows [w*16, w*16+16) x all 64 keys of the kv tile.
// SMEM row-major pitch 68 (fragment loads conflict-free / 2-way).
// ---------------------------------------------------------------------------
#define FP 68
__global__ __launch_bounds__(128, 1)
void fattn_mma(const float* __restrict__ Q, const float* __restrict__ K,
               const float* __restrict__ V, float* __restrict__ O,
               int win) {
    extern __shared__ float sm[];
    float (*Qs)[FP] = (float(*)[FP])sm;                   // [q][hd] tf32
    float (*Ks)[FP] = (float(*)[FP])(sm + 64 * FP);       // [key][hd] tf32
    float (*Vs)[FP] = (float(*)[FP])(sm + 2 * 64 * FP);   // [key][hd] tf32
    float (*Ps)[FP] = (float(*)[FP])(sm + 3 * 64 * FP);   // [q][key] tf32

    int qt  = gridDim.x - 1 - blockIdx.x;   // heavy tiles first
    int h   = blockIdx.y;
    int kvh = h >> 2;
    int tid = threadIdx.x;
    int wid = tid >> 5;
    int lane = tid & 31;
    int g  = lane >> 2;
    int cq = lane & 3;
    int m0 = wid * 16;
    int q0 = qt * 64;

    // stage Q (tf32)
    #pragma unroll
    for (int t = 0; t < 8; t++) {
        int idx = tid + t * 128;
        int qi = idx >> 4;
        int d4 = (idx & 15) << 2;
        float4 v4 = *(const float4*)(Q + (size_t)(q0 + qi) * DMODEL + h * HDIM + d4);
        uint4 u4 = make_uint4(f2tf32(v4.x), f2tf32(v4.y), f2tf32(v4.z), f2tf32(v4.w));
        *(uint4*)&Qs[qi][d4] = u4;
    }

    float o[8][4];
    #pragma unroll
    for (int u = 0; u < 8; u++)
        #pragma unroll
        for (int i = 0; i < 4; i++) o[u][i] = 0.0f;
    float mrow0 = -60.0f, mrow1 = -60.0f;
    float lrow0 = 0.0f,   lrow1 = 0.0f;

    int jt0 = 0;
    if (win > 0) { jt0 = qt - 4; if (jt0 < 0) jt0 = 0; }

    int row0 = q0 + m0 + g;
    int row1 = row0 + 8;

    __syncthreads();

    for (int jt = jt0; jt <= qt; jt++) {
        int j0 = jt * 64;
        // stage K, V (tf32)
        #pragma unroll
        for (int t = 0; t < 8; t++) {
            int idx = tid + t * 128;
            int jj = idx >> 4;
            int d4 = (idx & 15) << 2;
            size_t base = (size_t)(j0 + jj) * LATD + kvh * HDIM + d4;
            float4 k4 = *(const float4*)(K + base);
            float4 v4 = *(const float4*)(V + base);
            *(uint4*)&Ks[jj][d4] = make_uint4(f2tf32(k4.x), f2tf32(k4.y),
                                              f2tf32(k4.z), f2tf32(k4.w));
            *(uint4*)&Vs[jj][d4] = make_uint4(f2tf32(v4.x), f2tf32(v4.y),
                                              f2tf32(v4.z), f2tf32(v4.w));
        }
        __syncthreads();

        // S = Q K^T : acc fragments s[u] cover keys j0 + u*8..u*8+7
        float s[8][4];
        #pragma unroll
        for (int u = 0; u < 8; u++)
            #pragma unroll
            for (int i = 0; i < 4; i++) s[u][i] = 0.0f;

        #pragma unroll
        for (int k8 = 0; k8 < HDIM; k8 += 8) {
            uint32_t a0 = __float_as_uint(Qs[m0 + g    ][k8 + cq    ]);
            uint32_t a1 = __float_as_uint(Qs[m0 + g + 8][k8 + cq    ]);
            uint32_t a2 = __float_as_uint(Qs[m0 + g    ][k8 + cq + 4]);
            uint32_t a3 = __float_as_uint(Qs[m0 + g + 8][k8 + cq + 4]);
            #pragma unroll
            for (int u = 0; u < 8; u++) {
                uint32_t b0 = __float_as_uint(Ks[u * 8 + g][k8 + cq    ]);
                uint32_t b1 = __float_as_uint(Ks[u * 8 + g][k8 + cq + 4]);
                mma_tf32(s[u], a0, a1, a2, a3, b0, b1);
            }
        }

        // scale + mask
        #pragma unroll
        for (int u = 0; u < 8; u++) {
            int col = j0 + u * 8 + 2 * cq;
            #pragma unroll
            for (int i = 0; i < 4; i++) {
                int q  = (i < 2) ? row0 : row1;
                int kj = col + (i & 1);
                float val = s[u][i] * 0.125f;
                bool vis = (kj <= q) && (win == 0 || (q - kj) < win);
                s[u][i] = vis ? val : -1e30f;
            }
        }

        // online softmax (two rows per lane; quad reduce over cq)
        float rm0 = -1e30f, rm1 = -1e30f;
        #pragma unroll
        for (int u = 0; u < 8; u++) {
            rm0 = fmaxf(rm0, fmaxf(s[u][0], s[u][1]));
            rm1 = fmaxf(rm1, fmaxf(s[u][2], s[u][3]));
        }
        #pragma unroll
        for (int off = 1; off <= 2; off <<= 1) {
            rm0 = fmaxf(rm0, __shfl_xor_sync(0xffffffffu, rm0, off));
            rm1 = fmaxf(rm1, __shfl_xor_sync(0xffffffffu, rm1, off));
        }
        float mn0 = fmaxf(mrow0, rm0);
        float mn1 = fmaxf(mrow1, rm1);
        float al0 = __expf(mrow0 - mn0);
        float al1 = __expf(mrow1 - mn1);
        float rs0 = 0.0f, rs1 = 0.0f;
        #pragma unroll
        for (int u = 0; u < 8; u++) {
            float p0 = __expf(s[u][0] - mn0);
            float p1 = __expf(s[u][1] - mn0);
            float p2 = __expf(s[u][2] - mn1);
            float p3 = __expf(s[u][3] - mn1);
            s[u][0] = p0; s[u][1] = p1; s[u][2] = p2; s[u][3] = p3;
            rs0 += p0 + p1;
            rs1 += p2 + p3;
        }
        #pragma unroll
        for (int off = 1; off <= 2; off <<= 1) {
            rs0 += __shfl_xor_sync(0xffffffffu, rs0, off);
            rs1 += __shfl_xor_sync(0xffffffffu, rs1, off);
        }
        lrow0 = lrow0 * al0 + rs0;
        lrow1 = lrow1 * al1 + rs1;
        mrow0 = mn0;
        mrow1 = mn1;
        #pragma unroll
        for (int u = 0; u < 8; u++) {
            o[u][0] *= al0; o[u][1] *= al0;
            o[u][2] *= al1; o[u][3] *= al1;
        }

        // write P (tf32) to SMEM in [q][key] layout; same warp consumes it
        #pragma unroll
        for (int u = 0; u < 8; u++) {
            int col = u * 8 + 2 * cq;
            *(uint2*)&Ps[m0 + g    ][col] = make_uint2(f2tf32(s[u][0]), f2tf32(s[u][1]));
            *(uint2*)&Ps[m0 + g + 8][col] = make_uint2(f2tf32(s[u][2]), f2tf32(s[u][3]));
        }
        __syncwarp();

        // O += P @ V   (contraction over keys)
        #pragma unroll
        for (int k8 = 0; k8 < 64; k8 += 8) {
            uint32_t a0 = __float_as_uint(Ps[m0 + g    ][k8 + cq    ]);
            uint32_t a1 = __float_as_uint(Ps[m0 + g + 8][k8 + cq    ]);
            uint32_t a2 = __float_as_uint(Ps[m0 + g    ][k8 + cq + 4]);
            uint32_t a3 = __float_as_uint(Ps[m0 + g + 8][k8 + cq + 4]);
            #pragma unroll
            for (int u = 0; u < 8; u++) {
                uint32_t b0 = __float_as_uint(Vs[k8 + cq    ][u * 8 + g]);
                uint32_t b1 = __float_as_uint(Vs[k8 + cq + 4][u * 8 + g]);
                mma_tf32(o[u], a0, a1, a2, a3, b0, b1);
            }
        }
        __syncthreads();
    }

    float inv0 = 1.0f / lrow0;
    float inv1 = 1.0f / lrow1;
    #pragma unroll
    for (int u = 0; u < 8; u++) {
        int col = u * 8 + 2 * cq;
        *(float2*)(O + (size_t)row0 * DMODEL + h * HDIM + col) =
            make_float2(o[u][0] * inv0, o[u][1] * inv0);
        *(float2*)(O + (size_t)row1 * DMODEL + h * HDIM + col) =
            make_float2(o[u][2] * inv1, o[u][3] * inv1);
    }
}

// ---------------------------------------------------------------------------
// Launch
// ---------------------------------------------------------------------------
extern "C" void kernel_launch(void* const* d_in, const int* in_sizes, int n_in,
                              void* d_out, int out_size) {
    (void)in_sizes; (void)n_in; (void)out_size;

    const float* hidden   = (const float*)d_in[0];
    const float* norm1_w  = (const float*)d_in[1];
    const float* norm2_w  = (const float*)d_in[2];
    const float* w_g_wq   = (const float*)d_in[3];
    const float* w_g_kvdn = (const float*)d_in[4];
    const float* w_g_k_up = (const float*)d_in[5];
    const float* w_g_v_up = (const float*)d_in[6];
    const float* w_g_wo   = (const float*)d_in[7];
    const float* w_l_wq   = (const float*)d_in[8];
    const float* w_l_wk   = (const float*)d_in[9];
    const float* w_l_wv   = (const float*)d_in[10];
    const float* w_l_wo   = (const float*)d_in[11];
    float* out = (float*)d_out;

    float *x1, *q, *lat, *k, *v, *attn;
    cudaGetSymbolAddress((void**)&x1,   g_x1);
    cudaGetSymbolAddress((void**)&q,    g_q);
    cudaGetSymbolAddress((void**)&lat,  g_lat);
    cudaGetSymbolAddress((void**)&k,    g_k);
    cudaGetSymbolAddress((void**)&v,    g_v);
    cudaGetSymbolAddress((void**)&attn, g_attn);

    const int ATTN_SMEM = 4 * 64 * FP * sizeof(float);   // 69632
    cudaFuncSetAttribute(fattn_mma,
                         cudaFuncAttributeMaxDynamicSharedMemorySize, ATTN_SMEM);

    dim3 gridBig(DMODEL / 128, SEQ / 128);   // (8, 16)
    dim3 gridSm (LATD  / 64,  SEQ / 64);     // (4, 32)
    dim3 gridAttn(SEQ / 64, NH);             // (32, 16)

    // ---- Layer 1: global latent attention ----
    rmsnorm_kernel<<<SEQ, 256>>>(hidden, norm1_w, x1);
    mma_gemm<128,128,16><<<gridBig, 256>>>(x1,  w_g_wq,   nullptr, q,   DMODEL, DMODEL);
    mma_gemm<64,64,32>  <<<gridSm,  256>>>(x1,  w_g_kvdn, nullptr, lat, LATD,   DMODEL);
    mma_gemm<64,64,32>  <<<gridSm,  256>>>(lat, w_g_k_up, nullptr, k,   LATD,   LATD);
    mma_gemm<64,64,32>  <<<gridSm,  256>>>(lat, w_g_v_up, nullptr, v,   LATD,   LATD);
    rope_qknorm_kernel<<<dim3(SEQ, NH),   32>>>(q, NH,   1000000.0f);
    rope_qknorm_kernel<<<dim3(SEQ, NKVH), 32>>>(k, NKVH, 1000000.0f);
    fattn_mma<<<gridAttn, 128, ATTN_SMEM>>>(q, k, v, attn, /*win=*/0);
    mma_gemm<128,128,16><<<gridBig, 256>>>(attn, w_g_wo, hidden, out, DMODEL, DMODEL);

    // ---- Layer 2: local GQA attention ----
    rmsnorm_kernel<<<SEQ, 256>>>(out, norm2_w, x1);
    mma_gemm<128,128,16><<<gridBig, 256>>>(x1, w_l_wq, nullptr, q, DMODEL, DMODEL);
    mma_gemm<64,64,32>  <<<gridSm,  256>>>(x1, w_l_wk, nullptr, k, LATD, DMODEL);
    mma_gemm<64,64,32>  <<<gridSm,  256>>>(x1, w_l_wv, nullptr, v, LATD, DMODEL);
    rope_qknorm_kernel<<<dim3(SEQ, NH),   32>>>(q, NH,   10000.0f);
    rope_qknorm_kernel<<<dim3(SEQ, NKVH), 32>>>(k, NKVH, 10000.0f);
    fattn_mma<<<gridAttn, 128, ATTN_SMEM>>>(q, k, v, attn, /*win=*/WINSZ);
    mma_gemm<128,128,16><<<gridBig, 256>>>(attn, w_l_wo, out, out, DMODEL, DMODEL);
}

// round 9
// speedup vs baseline: 7.6132x; 1.0579x over previous
#include <cuda_runtime.h>
#include <math.h>
#include <stdint.h>

#define SEQ    2048
#define DMODEL 1024
#define NH     16
#define NKVH   4
#define HDIM   64
#define LATD   256
#define WINSZ  256

// ---------------------------------------------------------------------------
// Scratch (device globals; no allocation allowed)
// ---------------------------------------------------------------------------
__device__ float g_x1  [SEQ * DMODEL];
__device__ float g_q   [SEQ * DMODEL];
__device__ float g_lat [SEQ * LATD];
__device__ float g_k   [SEQ * LATD];
__device__ float g_v   [SEQ * LATD];
__device__ float g_attn[SEQ * DMODEL];

// ---------------------------------------------------------------------------
// Helpers
// ---------------------------------------------------------------------------
__device__ __forceinline__ uint32_t f2tf32(float x) {
    uint32_t u;
    asm("cvt.rna.tf32.f32 %0, %1;" : "=r"(u) : "f"(x));
    return u;
}

__device__ __forceinline__ void mma_tf32(float* c,
                                         uint32_t a0, uint32_t a1,
                                         uint32_t a2, uint32_t a3,
                                         uint32_t b0, uint32_t b1) {
    asm volatile(
        "mma.sync.aligned.m16n8k8.row.col.f32.tf32.tf32.f32 "
        "{%0,%1,%2,%3}, {%4,%5,%6,%7}, {%8,%9}, {%0,%1,%2,%3};\n"
        : "+f"(c[0]), "+f"(c[1]), "+f"(c[2]), "+f"(c[3])
        : "r"(a0), "r"(a1), "r"(a2), "r"(a3), "r"(b0), "r"(b1));
}

__device__ __forceinline__ void cp16(uint32_t s, const void* g) {
    asm volatile("cp.async.cg.shared.global [%0], [%1], 16;\n"
                 :: "r"(s), "l"(g));
}
__device__ __forceinline__ void cp_commit() {
    asm volatile("cp.async.commit_group;\n");
}
template<int N>
__device__ __forceinline__ void cp_wait() {
    asm volatile("cp.async.wait_group %0;\n" :: "n"(N));
}

// ---------------------------------------------------------------------------
// RMSNorm
// ---------------------------------------------------------------------------
__global__ void rmsnorm_kernel(const float* __restrict__ x,
                               const float* __restrict__ w,
                               float* __restrict__ y) {
    int row = blockIdx.x;
    int tid = threadIdx.x;
    const float4* xr = (const float4*)(x + (size_t)row * DMODEL);
    float4 v = xr[tid];
    float ss = v.x * v.x + v.y * v.y + v.z * v.z + v.w * v.w;
    __shared__ float red[256];
    red[tid] = ss;
    __syncthreads();
    #pragma unroll
    for (int o = 128; o > 0; o >>= 1) {
        if (tid < o) red[tid] += red[tid + o];
        __syncthreads();
    }
    float r = rsqrtf(red[0] / (float)DMODEL + 1e-6f);
    float4 wv = ((const float4*)w)[tid];
    float4 o4 = make_float4(v.x * r * wv.x, v.y * r * wv.y,
                            v.z * r * wv.z, v.w * r * wv.w);
    ((float4*)(y + (size_t)row * DMODEL))[tid] = o4;
}

// ---------------------------------------------------------------------------
// Segmented TF32 GEMM with cp.async 2-stage pipeline.
// C_seg[M, n_seg] = A[M,K] @ B_seg[K, n_seg] (+ R for single-segment)
// Up to 3 column segments concatenated along grid.x. BN=64 divides all widths.
// A kept row-major [m][k] in SMEM (cp.async, no transpose); tf32 rounding at
// fragment build. 256 threads = 8 warps (4m x 2n).
// ---------------------------------------------------------------------------
template<int BM, int BN, int BK>
__global__ __launch_bounds__(256)
void mma_gemm(const float* __restrict__ A,
              const float* __restrict__ B0, float* __restrict__ C0, int n0,
              const float* __restrict__ B1, float* __restrict__ C1, int n1,
              const float* __restrict__ B2, float* __restrict__ C2, int n2,
              const float* __restrict__ R, int K) {
    constexpr int AP  = BK + 4;
    constexpr int BP  = BN + 4;
    constexpr int WM  = BM / 4;
    constexpr int WN  = BN / 2;
    constexpr int MT  = WM / 16;
    constexpr int NT  = WN / 8;
    constexpr int AF4 = BM * BK / 1024;   // float4 A-copies / thread / stage
    constexpr int BF4 = BK * BN / 1024;
    constexpr int AKC = BK / 4;
    constexpr int BNC = BN / 4;

    extern __shared__ float smem[];
    float (*As)[BM][AP] = (float(*)[BM][AP])smem;              // [2][BM][AP]
    float (*Bs)[BK][BP] = (float(*)[BK][BP])(smem + 2 * BM * AP);

    int tid  = threadIdx.x;
    int wid  = tid >> 5;
    int lane = tid & 31;
    int g    = lane >> 2;
    int cq   = lane & 3;
    int wm   = (wid >> 1) * WM;
    int wn   = (wid & 1) * WN;
    int r0   = blockIdx.y * BM;
    int c0   = blockIdx.x * BN;

    const float* Bseg;
    float* Cseg;
    int nseg, segc;
    if (c0 < n0)           { Bseg = B0; Cseg = C0; nseg = n0; segc = c0; }
    else if (c0 < n0 + n1) { Bseg = B1; Cseg = C1; nseg = n1; segc = c0 - n0; }
    else                   { Bseg = B2; Cseg = C2; nseg = n2; segc = c0 - n0 - n1; }

    float acc[MT][NT][4];
    #pragma unroll
    for (int t = 0; t < MT; t++)
        #pragma unroll
        for (int u = 0; u < NT; u++)
            #pragma unroll
            for (int i = 0; i < 4; i++) acc[t][u][i] = 0.0f;

    // stage k-block 0
    #pragma unroll
    for (int t = 0; t < AF4; t++) {
        int idx = tid + t * 256;
        int ar = idx / AKC, ac = (idx % AKC) * 4;
        cp16((uint32_t)__cvta_generic_to_shared(&As[0][ar][ac]),
             A + (size_t)(r0 + ar) * K + ac);
    }
    #pragma unroll
    for (int t = 0; t < BF4; t++) {
        int idx = tid + t * 256;
        int br = idx / BNC, bc = (idx % BNC) * 4;
        cp16((uint32_t)__cvta_generic_to_shared(&Bs[0][br][bc]),
             Bseg + (size_t)br * nseg + segc + bc);
    }
    cp_commit();

    int NKB = K / BK;
    for (int kb = 0; kb < NKB; kb++) {
        int b = kb & 1;
        if (kb + 1 < NKB) {
            int k0 = (kb + 1) * BK;
            #pragma unroll
            for (int t = 0; t < AF4; t++) {
                int idx = tid + t * 256;
                int ar = idx / AKC, ac = (idx % AKC) * 4;
                cp16((uint32_t)__cvta_generic_to_shared(&As[b ^ 1][ar][ac]),
                     A + (size_t)(r0 + ar) * K + k0 + ac);
            }
            #pragma unroll
            for (int t = 0; t < BF4; t++) {
                int idx = tid + t * 256;
                int br = idx / BNC, bc = (idx % BNC) * 4;
                cp16((uint32_t)__cvta_generic_to_shared(&Bs[b ^ 1][br][bc]),
                     Bseg + (size_t)(k0 + br) * nseg + segc + bc);
            }
            cp_commit();
            cp_wait<1>();
        } else {
            cp_wait<0>();
        }
        __syncthreads();

        #pragma unroll
        for (int k8 = 0; k8 < BK; k8 += 8) {
            uint32_t af[MT][4];
            #pragma unroll
            for (int t = 0; t < MT; t++) {
                int m0 = wm + 16 * t + g;
                af[t][0] = f2tf32(As[b][m0    ][k8 + cq    ]);
                af[t][1] = f2tf32(As[b][m0 + 8][k8 + cq    ]);
                af[t][2] = f2tf32(As[b][m0    ][k8 + cq + 4]);
                af[t][3] = f2tf32(As[b][m0 + 8][k8 + cq + 4]);
            }
            uint32_t bf[NT][2];
            #pragma unroll
            for (int u = 0; u < NT; u++) {
                int nn = wn + 8 * u + g;
                bf[u][0] = f2tf32(Bs[b][k8 + cq    ][nn]);
                bf[u][1] = f2tf32(Bs[b][k8 + cq + 4][nn]);
            }
            #pragma unroll
            for (int t = 0; t < MT; t++)
                #pragma unroll
                for (int u = 0; u < NT; u++)
                    mma_tf32(acc[t][u], af[t][0], af[t][1], af[t][2], af[t][3],
                             bf[u][0], bf[u][1]);
        }
        __syncthreads();
    }

    #pragma unroll
    for (int t = 0; t < MT; t++) {
        int row = r0 + wm + 16 * t + g;
        #pragma unroll
        for (int u = 0; u < NT; u++) {
            int col = segc + wn + 8 * u + 2 * cq;
            size_t off0 = (size_t)row * nseg + col;
            size_t off1 = (size_t)(row + 8) * nseg + col;
            float2 r0v = make_float2(0.f, 0.f), r1v = make_float2(0.f, 0.f);
            if (R) {
                r0v = *(const float2*)(R + off0);
                r1v = *(const float2*)(R + off1);
            }
            *(float2*)(Cseg + off0) = make_float2(acc[t][u][0] + r0v.x,
                                                  acc[t][u][1] + r0v.y);
            *(float2*)(Cseg + off1) = make_float2(acc[t][u][2] + r1v.x,
                                                  acc[t][u][3] + r1v.y);
        }
    }
}

// ---------------------------------------------------------------------------
// Merged RoPE + qk_norm for Q (16 heads) and K (4 heads) in one launch.
// Grid: (SEQ, NH + NKVH), 32 threads.
// ---------------------------------------------------------------------------
__global__ void rope_qknorm2(float* __restrict__ q, float* __restrict__ k,
                             float base) {
    int s  = blockIdx.x;
    int hh = blockIdx.y;
    int i  = threadIdx.x;
    float* p = (hh < NH)
        ? q + (size_t)s * DMODEL + hh * HDIM
        : k + (size_t)s * LATD + (hh - NH) * HDIM;

    float invf = powf(base, -((float)(2 * i) / (float)HDIM));
    float ang = (float)s * invf;
    float sn, cs;
    sincosf(ang, &sn, &cs);

    float xe = p[2 * i];
    float xo = p[2 * i + 1];
    float re = xe * cs - xo * sn;
    float ro = xe * sn + xo * cs;

    float ss = re * re + ro * ro;
    #pragma unroll
    for (int o = 16; o > 0; o >>= 1)
        ss += __shfl_xor_sync(0xffffffffu, ss, o);

    float r = rsqrtf(ss / (float)HDIM + 1e-6f);
    p[2 * i]     = re * r;
    p[2 * i + 1] = ro * r;
}

// ---------------------------------------------------------------------------
// TF32 mma flash attention with cp.async double-buffered K/V.
// Block = (64-query tile, head), 128 threads / 4 warps.
// SMEM: Qs[64][68] Ps[64][68] Ks[2][64][68] Vs[2][64][68]  (104448 B)
// ---------------------------------------------------------------------------
#define FP 68
__global__ __launch_bounds__(128, 1)
void fattn_mma(const float* __restrict__ Q, const float* __restrict__ K,
               const float* __restrict__ V, float* __restrict__ O,
               int win) {
    extern __shared__ float sm[];
    float (*Qs)[FP]     = (float(*)[FP])sm;
    float (*Ps)[FP]     = (float(*)[FP])(sm + 64 * FP);
    float (*Ks)[64][FP] = (float(*)[64][FP])(sm + 2 * 64 * FP);
    float (*Vs)[64][FP] = (float(*)[64][FP])(sm + 4 * 64 * FP);

    int qt  = gridDim.x - 1 - blockIdx.x;   // heavy tiles first
    int h   = blockIdx.y;
    int kvh = h >> 2;
    int tid = threadIdx.x;
    int wid = tid >> 5;
    int lane = tid & 31;
    int g  = lane >> 2;
    int cq = lane & 3;
    int m0 = wid * 16;
    int q0 = qt * 64;

    int jt0 = 0;
    if (win > 0) { jt0 = qt - 4; if (jt0 < 0) jt0 = 0; }

    // issue K/V stage for first kv tile
    {
        int j0 = jt0 * 64;
        #pragma unroll
        for (int t = 0; t < 8; t++) {
            int idx = tid + t * 128;
            int jj = idx >> 4, d4 = (idx & 15) << 2;
            size_t base = (size_t)(j0 + jj) * LATD + kvh * HDIM + d4;
            cp16((uint32_t)__cvta_generic_to_shared(&Ks[0][jj][d4]), K + base);
            cp16((uint32_t)__cvta_generic_to_shared(&Vs[0][jj][d4]), V + base);
        }
        cp_commit();
    }

    // stage Q (tf32, once) while K/V copies fly
    #pragma unroll
    for (int t = 0; t < 8; t++) {
        int idx = tid + t * 128;
        int qi = idx >> 4, d4 = (idx & 15) << 2;
        float4 v4 = *(const float4*)(Q + (size_t)(q0 + qi) * DMODEL + h * HDIM + d4);
        *(uint4*)&Qs[qi][d4] = make_uint4(f2tf32(v4.x), f2tf32(v4.y),
                                          f2tf32(v4.z), f2tf32(v4.w));
    }

    float o[8][4];
    #pragma unroll
    for (int u = 0; u < 8; u++)
        #pragma unroll
        for (int i = 0; i < 4; i++) o[u][i] = 0.0f;
    float mrow0 = -60.0f, mrow1 = -60.0f;
    float lrow0 = 0.0f,   lrow1 = 0.0f;

    int row0 = q0 + m0 + g;
    int row1 = row0 + 8;

    for (int jt = jt0; jt <= qt; jt++) {
        int b = (jt - jt0) & 1;
        if (jt < qt) {
            int j0 = (jt + 1) * 64;
            #pragma unroll
            for (int t = 0; t < 8; t++) {
                int idx = tid + t * 128;
                int jj = idx >> 4, d4 = (idx & 15) << 2;
                size_t base = (size_t)(j0 + jj) * LATD + kvh * HDIM + d4;
                cp16((uint32_t)__cvta_generic_to_shared(&Ks[b ^ 1][jj][d4]), K + base);
                cp16((uint32_t)__cvta_generic_to_shared(&Vs[b ^ 1][jj][d4]), V + base);
            }
            cp_commit();
            cp_wait<1>();
        } else {
            cp_wait<0>();
        }
        __syncthreads();

        int j0 = jt * 64;

        // S = Q K^T
        float s[8][4];
        #pragma unroll
        for (int u = 0; u < 8; u++)
            #pragma unroll
            for (int i = 0; i < 4; i++) s[u][i] = 0.0f;

        #pragma unroll
        for (int k8 = 0; k8 < HDIM; k8 += 8) {
            uint32_t a0 = __float_as_uint(Qs[m0 + g    ][k8 + cq    ]);
            uint32_t a1 = __float_as_uint(Qs[m0 + g + 8][k8 + cq    ]);
            uint32_t a2 = __float_as_uint(Qs[m0 + g    ][k8 + cq + 4]);
            uint32_t a3 = __float_as_uint(Qs[m0 + g + 8][k8 + cq + 4]);
            #pragma unroll
            for (int u = 0; u < 8; u++) {
                uint32_t b0 = f2tf32(Ks[b][u * 8 + g][k8 + cq    ]);
                uint32_t b1 = f2tf32(Ks[b][u * 8 + g][k8 + cq + 4]);
                mma_tf32(s[u], a0, a1, a2, a3, b0, b1);
            }
        }

        // scale + mask
        #pragma unroll
        for (int u = 0; u < 8; u++) {
            int col = j0 + u * 8 + 2 * cq;
            #pragma unroll
            for (int i = 0; i < 4; i++) {
                int q  = (i < 2) ? row0 : row1;
                int kj = col + (i & 1);
                float val = s[u][i] * 0.125f;
                bool vis = (kj <= q) && (win == 0 || (q - kj) < win);
                s[u][i] = vis ? val : -1e30f;
            }
        }

        // online softmax
        float rm0 = -1e30f, rm1 = -1e30f;
        #pragma unroll
        for (int u = 0; u < 8; u++) {
            rm0 = fmaxf(rm0, fmaxf(s[u][0], s[u][1]));
            rm1 = fmaxf(rm1, fmaxf(s[u][2], s[u][3]));
        }
        #pragma unroll
        for (int off = 1; off <= 2; off <<= 1) {
            rm0 = fmaxf(rm0, __shfl_xor_sync(0xffffffffu, rm0, off));
            rm1 = fmaxf(rm1, __shfl_xor_sync(0xffffffffu, rm1, off));
        }
        float mn0 = fmaxf(mrow0, rm0);
        float mn1 = fmaxf(mrow1, rm1);
        float al0 = __expf(mrow0 - mn0);
        float al1 = __expf(mrow1 - mn1);
        float rs0 = 0.0f, rs1 = 0.0f;
        #pragma unroll
        for (int u = 0; u < 8; u++) {
            float p0 = __expf(s[u][0] - mn0);
            float p1 = __expf(s[u][1] - mn0);
            float p2 = __expf(s[u][2] - mn1);
            float p3 = __expf(s[u][3] - mn1);
            s[u][0] = p0; s[u][1] = p1; s[u][2] = p2; s[u][3] = p3;
            rs0 += p0 + p1;
            rs1 += p2 + p3;
        }
        #pragma unroll
        for (int off = 1; off <= 2; off <<= 1) {
            rs0 += __shfl_xor_sync(0xffffffffu, rs0, off);
            rs1 += __shfl_xor_sync(0xffffffffu, rs1, off);
        }
        lrow0 = lrow0 * al0 + rs0;
        lrow1 = lrow1 * al1 + rs1;
        mrow0 = mn0;
        mrow1 = mn1;
        #pragma unroll
        for (int u = 0; u < 8; u++) {
            o[u][0] *= al0; o[u][1] *= al0;
            o[u][2] *= al1; o[u][3] *= al1;
        }

        // P -> SMEM (tf32), same warp consumes
        #pragma unroll
        for (int u = 0; u < 8; u++) {
            int col = u * 8 + 2 * cq;
            *(uint2*)&Ps[m0 + g    ][col] = make_uint2(f2tf32(s[u][0]), f2tf32(s[u][1]));
            *(uint2*)&Ps[m0 + g + 8][col] = make_uint2(f2tf32(s[u][2]), f2tf32(s[u][3]));
        }
        __syncwarp();

        // O += P @ V
        #pragma unroll
        for (int k8 = 0; k8 < 64; k8 += 8) {
            uint32_t a0 = __float_as_uint(Ps[m0 + g    ][k8 + cq    ]);
            uint32_t a1 = __float_as_uint(Ps[m0 + g + 8][k8 + cq    ]);
            uint32_t a2 = __float_as_uint(Ps[m0 + g    ][k8 + cq + 4]);
            uint32_t a3 = __float_as_uint(Ps[m0 + g + 8][k8 + cq + 4]);
            #pragma unroll
            for (int u = 0; u < 8; u++) {
                uint32_t b0 = f2tf32(Vs[b][k8 + cq    ][u * 8 + g]);
                uint32_t b1 = f2tf32(Vs[b][k8 + cq + 4][u * 8 + g]);
                mma_tf32(o[u], a0, a1, a2, a3, b0, b1);
            }
        }
        __syncthreads();
    }

    float inv0 = 1.0f / lrow0;
    float inv1 = 1.0f / lrow1;
    #pragma unroll
    for (int u = 0; u < 8; u++) {
        int col = u * 8 + 2 * cq;
        *(float2*)(O + (size_t)row0 * DMODEL + h * HDIM + col) =
            make_float2(o[u][0] * inv0, o[u][1] * inv0);
        *(float2*)(O + (size_t)row1 * DMODEL + h * HDIM + col) =
            make_float2(o[u][2] * inv1, o[u][3] * inv1);
    }
}

// ---------------------------------------------------------------------------
// Launch
// ---------------------------------------------------------------------------
extern "C" void kernel_launch(void* const* d_in, const int* in_sizes, int n_in,
                              void* d_out, int out_size) {
    (void)in_sizes; (void)n_in; (void)out_size;

    const float* hidden   = (const float*)d_in[0];
    const float* norm1_w  = (const float*)d_in[1];
    const float* norm2_w  = (const float*)d_in[2];
    const float* w_g_wq   = (const float*)d_in[3];
    const float* w_g_kvdn = (const float*)d_in[4];
    const float* w_g_k_up = (const float*)d_in[5];
    const float* w_g_v_up = (const float*)d_in[6];
    const float* w_g_wo   = (const float*)d_in[7];
    const float* w_l_wq   = (const float*)d_in[8];
    const float* w_l_wk   = (const float*)d_in[9];
    const float* w_l_wv   = (const float*)d_in[10];
    const float* w_l_wo   = (const float*)d_in[11];
    float* out = (float*)d_out;

    float *x1, *q, *lat, *k, *v, *attn;
    cudaGetSymbolAddress((void**)&x1,   g_x1);
    cudaGetSymbolAddress((void**)&q,    g_q);
    cudaGetSymbolAddress((void**)&lat,  g_lat);
    cudaGetSymbolAddress((void**)&k,    g_k);
    cudaGetSymbolAddress((void**)&v,    g_v);
    cudaGetSymbolAddress((void**)&attn, g_attn);

    // SMEM sizes
    const int GEMM128_SMEM = (2 * 128 * 36 + 2 * 32 * 68) * sizeof(float); // 54272
    const int GEMM64_SMEM  = (2 * 64 * 36 + 2 * 32 * 68) * sizeof(float);  // 35840
    const int ATTN_SMEM    = 6 * 64 * FP * sizeof(float);                  // 104448

    cudaFuncSetAttribute(mma_gemm<128, 64, 32>,
                         cudaFuncAttributeMaxDynamicSharedMemorySize, GEMM128_SMEM);
    cudaFuncSetAttribute(mma_gemm<64, 64, 32>,
                         cudaFuncAttributeMaxDynamicSharedMemorySize, GEMM64_SMEM);
    cudaFuncSetAttribute(fattn_mma,
                         cudaFuncAttributeMaxDynamicSharedMemorySize, ATTN_SMEM);

    dim3 gridAttn(SEQ / 64, NH);

    // ---- Layer 1: global latent attention ----
    rmsnorm_kernel<<<SEQ, 256>>>(hidden, norm1_w, x1);
    // {wq -> q (1024)} ++ {kv_down -> lat (256)}, A = x1, K = 1024
    mma_gemm<128, 64, 32><<<dim3(20, 16), 256, GEMM128_SMEM>>>(
        x1, w_g_wq, q, DMODEL, w_g_kvdn, lat, LATD,
        nullptr, nullptr, 0, nullptr, DMODEL);
    // {k_up -> k (256)} ++ {v_up -> v (256)}, A = lat, K = 256
    mma_gemm<64, 64, 32><<<dim3(8, 32), 256, GEMM64_SMEM>>>(
        lat, w_g_k_up, k, LATD, w_g_v_up, v, LATD,
        nullptr, nullptr, 0, nullptr, LATD);
    rope_qknorm2<<<dim3(SEQ, NH + NKVH), 32>>>(q, k, 1000000.0f);
    fattn_mma<<<gridAttn, 128, ATTN_SMEM>>>(q, k, v, attn, /*win=*/0);
    // out = attn @ g_wo + hidden
    mma_gemm<128, 64, 32><<<dim3(16, 16), 256, GEMM128_SMEM>>>(
        attn, w_g_wo, out, DMODEL, nullptr, nullptr, 0,
        nullptr, nullptr, 0, hidden, DMODEL);

    // ---- Layer 2: local GQA attention ----
    rmsnorm_kernel<<<SEQ, 256>>>(out, norm2_w, x1);
    // {wq -> q (1024)} ++ {wk -> k (256)} ++ {wv -> v (256)}, A = x1, K = 1024
    mma_gemm<128, 64, 32><<<dim3(24, 16), 256, GEMM128_SMEM>>>(
        x1, w_l_wq, q, DMODEL, w_l_wk, k, LATD,
        w_l_wv, v, LATD, nullptr, DMODEL);
    rope_qknorm2<<<dim3(SEQ, NH + NKVH), 32>>>(q, k, 10000.0f);
    fattn_mma<<<gridAttn, 128, ATTN_SMEM>>>(q, k, v, attn, /*win=*/WINSZ);
    // out = attn @ l_wo + out
    mma_gemm<128, 64, 32><<<dim3(16, 16), 256, GEMM128_SMEM>>>(
        attn, w_l_wo, out, DMODEL, nullptr, nullptr, 0,
        nullptr, nullptr, 0, out, DMODEL);
}

// round 10
// speedup vs baseline: 9.2757x; 1.2184x over previous
#include <cuda_runtime.h>
#include <math.h>
#include <stdint.h>

#define SEQ    2048
#define DMODEL 1024
#define NH     16
#define NKVH   4
#define HDIM   64
#define LATD   256
#define WINSZ  256

// ---------------------------------------------------------------------------
// Scratch (device globals; no allocation allowed)
// ---------------------------------------------------------------------------
__device__ float g_x1  [SEQ * DMODEL];
__device__ float g_q   [SEQ * DMODEL];
__device__ float g_lat [SEQ * LATD];
__device__ float g_k   [SEQ * LATD];
__device__ float g_v   [SEQ * LATD];
__device__ float g_attn[SEQ * DMODEL];

// tf32-rounded weights, concatenated
#define GWQ  0
#define GKV  1048576
#define GKUP 1310720
#define GVUP 1376256
#define GWO  1441792
#define LWQ  2490368
#define LWK  3538944
#define LWV  3801088
#define LWO  4063232
__device__ float g_w[5111808];

// ---------------------------------------------------------------------------
// Helpers
// ---------------------------------------------------------------------------
__device__ __forceinline__ uint32_t f2tf32(float x) {
    uint32_t u;
    asm("cvt.rna.tf32.f32 %0, %1;" : "=r"(u) : "f"(x));
    return u;
}
__device__ __forceinline__ float tf32f(float x) {
    return __uint_as_float(f2tf32(x));
}

__device__ __forceinline__ void mma_tf32(float* c,
                                         uint32_t a0, uint32_t a1,
                                         uint32_t a2, uint32_t a3,
                                         uint32_t b0, uint32_t b1) {
    asm volatile(
        "mma.sync.aligned.m16n8k8.row.col.f32.tf32.tf32.f32 "
        "{%0,%1,%2,%3}, {%4,%5,%6,%7}, {%8,%9}, {%0,%1,%2,%3};\n"
        : "+f"(c[0]), "+f"(c[1]), "+f"(c[2]), "+f"(c[3])
        : "r"(a0), "r"(a1), "r"(a2), "r"(a3), "r"(b0), "r"(b1));
}

__device__ __forceinline__ void cp16(uint32_t s, const void* g) {
    asm volatile("cp.async.cg.shared.global [%0], [%1], 16;\n"
                 :: "r"(s), "l"(g));
}
__device__ __forceinline__ void cp_commit() {
    asm volatile("cp.async.commit_group;\n");
}
template<int N>
__device__ __forceinline__ void cp_wait() {
    asm volatile("cp.async.wait_group %0;\n" :: "n"(N));
}

// ---------------------------------------------------------------------------
// Round 5 input segments to tf32 into one contiguous output. Sizes in float4.
// ---------------------------------------------------------------------------
__global__ void round_tf32_5(float4* __restrict__ out,
                             const float4* p0, int n0,
                             const float4* p1, int n1,
                             const float4* p2, int n2,
                             const float4* p3, int n3,
                             const float4* p4, int n4) {
    int i = blockIdx.x * blockDim.x + threadIdx.x;
    int t0 = n0, t1 = t0 + n1, t2 = t1 + n2, t3 = t2 + n3, t4 = t3 + n4;
    if (i >= t4) return;
    const float4* src;
    int j;
    if (i < t0)      { src = p0; j = i; }
    else if (i < t1) { src = p1; j = i - t0; }
    else if (i < t2) { src = p2; j = i - t1; }
    else if (i < t3) { src = p3; j = i - t2; }
    else             { src = p4; j = i - t3; }
    float4 v = src[j];
    out[i] = make_float4(tf32f(v.x), tf32f(v.y), tf32f(v.z), tf32f(v.w));
}

// ---------------------------------------------------------------------------
// RMSNorm -> tf32-rounded output (feeds GEMM A operands only)
// ---------------------------------------------------------------------------
__global__ void rmsnorm_kernel(const float* __restrict__ x,
                               const float* __restrict__ w,
                               float* __restrict__ y) {
    int row = blockIdx.x;
    int tid = threadIdx.x;
    const float4* xr = (const float4*)(x + (size_t)row * DMODEL);
    float4 v = xr[tid];
    float ss = v.x * v.x + v.y * v.y + v.z * v.z + v.w * v.w;
    __shared__ float red[256];
    red[tid] = ss;
    __syncthreads();
    #pragma unroll
    for (int o = 128; o > 0; o >>= 1) {
        if (tid < o) red[tid] += red[tid + o];
        __syncthreads();
    }
    float r = rsqrtf(red[0] / (float)DMODEL + 1e-6f);
    float4 wv = ((const float4*)w)[tid];
    float4 o4 = make_float4(tf32f(v.x * r * wv.x), tf32f(v.y * r * wv.y),
                            tf32f(v.z * r * wv.z), tf32f(v.w * r * wv.w));
    ((float4*)(y + (size_t)row * DMODEL))[tid] = o4;
}

// ---------------------------------------------------------------------------
// Segmented TF32 GEMM, cp.async 2-stage. All operands pre-rounded to tf32,
// fragments consume raw bits (no in-loop cvt). rflags bit s => round seg s
// output to tf32 (it feeds another mma).
// ---------------------------------------------------------------------------
template<int BM, int BN, int BK>
__global__ __launch_bounds__(256)
void mma_gemm(const float* __restrict__ A,
              const float* __restrict__ B0, float* __restrict__ C0, int n0,
              const float* __restrict__ B1, float* __restrict__ C1, int n1,
              const float* __restrict__ B2, float* __restrict__ C2, int n2,
              const float* __restrict__ R, int K, int rflags) {
    constexpr int AP  = BK + 4;
    constexpr int BP  = BN + 4;
    constexpr int WM  = BM / 4;
    constexpr int WN  = BN / 2;
    constexpr int MT  = WM / 16;
    constexpr int NT  = WN / 8;
    constexpr int AF4 = BM * BK / 1024;
    constexpr int BF4 = BK * BN / 1024;
    constexpr int AKC = BK / 4;
    constexpr int BNC = BN / 4;

    extern __shared__ float smem[];
    float (*As)[BM][AP] = (float(*)[BM][AP])smem;
    float (*Bs)[BK][BP] = (float(*)[BK][BP])(smem + 2 * BM * AP);

    int tid  = threadIdx.x;
    int wid  = tid >> 5;
    int lane = tid & 31;
    int g    = lane >> 2;
    int cq   = lane & 3;
    int wm   = (wid >> 1) * WM;
    int wn   = (wid & 1) * WN;
    int r0   = blockIdx.y * BM;
    int c0   = blockIdx.x * BN;

    const float* Bseg;
    float* Cseg;
    int nseg, segc, segi;
    if (c0 < n0)           { Bseg = B0; Cseg = C0; nseg = n0; segc = c0; segi = 0; }
    else if (c0 < n0 + n1) { Bseg = B1; Cseg = C1; nseg = n1; segc = c0 - n0; segi = 1; }
    else                   { Bseg = B2; Cseg = C2; nseg = n2; segc = c0 - n0 - n1; segi = 2; }
    bool rnd = (rflags >> segi) & 1;

    float acc[MT][NT][4];
    #pragma unroll
    for (int t = 0; t < MT; t++)
        #pragma unroll
        for (int u = 0; u < NT; u++)
            #pragma unroll
            for (int i = 0; i < 4; i++) acc[t][u][i] = 0.0f;

    #pragma unroll
    for (int t = 0; t < AF4; t++) {
        int idx = tid + t * 256;
        int ar = idx / AKC, ac = (idx % AKC) * 4;
        cp16((uint32_t)__cvta_generic_to_shared(&As[0][ar][ac]),
             A + (size_t)(r0 + ar) * K + ac);
    }
    #pragma unroll
    for (int t = 0; t < BF4; t++) {
        int idx = tid + t * 256;
        int br = idx / BNC, bc = (idx % BNC) * 4;
        cp16((uint32_t)__cvta_generic_to_shared(&Bs[0][br][bc]),
             Bseg + (size_t)br * nseg + segc + bc);
    }
    cp_commit();

    int NKB = K / BK;
    for (int kb = 0; kb < NKB; kb++) {
        int b = kb & 1;
        if (kb + 1 < NKB) {
            int k0 = (kb + 1) * BK;
            #pragma unroll
            for (int t = 0; t < AF4; t++) {
                int idx = tid + t * 256;
                int ar = idx / AKC, ac = (idx % AKC) * 4;
                cp16((uint32_t)__cvta_generic_to_shared(&As[b ^ 1][ar][ac]),
                     A + (size_t)(r0 + ar) * K + k0 + ac);
            }
            #pragma unroll
            for (int t = 0; t < BF4; t++) {
                int idx = tid + t * 256;
                int br = idx / BNC, bc = (idx % BNC) * 4;
                cp16((uint32_t)__cvta_generic_to_shared(&Bs[b ^ 1][br][bc]),
                     Bseg + (size_t)(k0 + br) * nseg + segc + bc);
            }
            cp_commit();
            cp_wait<1>();
        } else {
            cp_wait<0>();
        }
        __syncthreads();

        #pragma unroll
        for (int k8 = 0; k8 < BK; k8 += 8) {
            uint32_t af[MT][4];
            #pragma unroll
            for (int t = 0; t < MT; t++) {
                int m0 = wm + 16 * t + g;
                af[t][0] = __float_as_uint(As[b][m0    ][k8 + cq    ]);
                af[t][1] = __float_as_uint(As[b][m0 + 8][k8 + cq    ]);
                af[t][2] = __float_as_uint(As[b][m0    ][k8 + cq + 4]);
                af[t][3] = __float_as_uint(As[b][m0 + 8][k8 + cq + 4]);
            }
            uint32_t bf[NT][2];
            #pragma unroll
            for (int u = 0; u < NT; u++) {
                int nn = wn + 8 * u + g;
                bf[u][0] = __float_as_uint(Bs[b][k8 + cq    ][nn]);
                bf[u][1] = __float_as_uint(Bs[b][k8 + cq + 4][nn]);
            }
            #pragma unroll
            for (int t = 0; t < MT; t++)
                #pragma unroll
                for (int u = 0; u < NT; u++)
                    mma_tf32(acc[t][u], af[t][0], af[t][1], af[t][2], af[t][3],
                             bf[u][0], bf[u][1]);
        }
        __syncthreads();
    }

    #pragma unroll
    for (int t = 0; t < MT; t++) {
        int row = r0 + wm + 16 * t + g;
        #pragma unroll
        for (int u = 0; u < NT; u++) {
            int col = segc + wn + 8 * u + 2 * cq;
            size_t off0 = (size_t)row * nseg + col;
            size_t off1 = (size_t)(row + 8) * nseg + col;
            float2 r0v = make_float2(0.f, 0.f), r1v = make_float2(0.f, 0.f);
            if (R) {
                r0v = *(const float2*)(R + off0);
                r1v = *(const float2*)(R + off1);
            }
            float o00 = acc[t][u][0] + r0v.x, o01 = acc[t][u][1] + r0v.y;
            float o10 = acc[t][u][2] + r1v.x, o11 = acc[t][u][3] + r1v.y;
            if (rnd) {
                o00 = tf32f(o00); o01 = tf32f(o01);
                o10 = tf32f(o10); o11 = tf32f(o11);
            }
            *(float2*)(Cseg + off0) = make_float2(o00, o01);
            *(float2*)(Cseg + off1) = make_float2(o10, o11);
        }
    }
}

// ---------------------------------------------------------------------------
// Fast RoPE + qk_norm: one block per s, 20 warps = 20 heads (16 Q + 4 K).
// 32 lanes compute the shared sincos table once. Q additionally scaled by
// 1/8 (exact power of two, folded softmax scale). Outputs tf32-rounded.
// ---------------------------------------------------------------------------
__global__ __launch_bounds__(640)
void rope_qknorm_fast(float* __restrict__ q, float* __restrict__ k,
                      float base) {
    __shared__ float scs[32], ssn[32];
    int s   = blockIdx.x;
    int tid = threadIdx.x;
    int w   = tid >> 5;
    int i   = tid & 31;

    if (tid < 32) {
        float invf = powf(base, -((float)(2 * tid) / (float)HDIM));
        float ang = (float)s * invf;
        sincosf(ang, &ssn[tid], &scs[tid]);
    }
    __syncthreads();

    float* p;
    float scale;
    if (w < NH) { p = q + (size_t)s * DMODEL + w * HDIM; scale = 0.125f; }
    else        { p = k + (size_t)s * LATD + (w - NH) * HDIM; scale = 1.0f; }

    float2 xv = *(float2*)(p + 2 * i);
    float cs = scs[i], sn = ssn[i];
    float re = xv.x * cs - xv.y * sn;
    float ro = xv.x * sn + xv.y * cs;

    float ss = re * re + ro * ro;
    #pragma unroll
    for (int o = 16; o > 0; o >>= 1)
        ss += __shfl_xor_sync(0xffffffffu, ss, o);

    float r = rsqrtf(ss / (float)HDIM + 1e-6f) * scale;
    *(float2*)(p + 2 * i) = make_float2(tf32f(re * r), tf32f(ro * r));
}

// ---------------------------------------------------------------------------
// TF32 mma flash attention, cp.async double-buffered K/V, hoisted Q frags.
// Q pre-scaled by 1/8; Q/K/V already tf32 -> raw fragment bits.
// Output tf32-rounded (feeds wo GEMM).
// ---------------------------------------------------------------------------
#define FP 68
__global__ __launch_bounds__(128, 1)
void fattn_mma(const float* __restrict__ Q, const float* __restrict__ K,
               const float* __restrict__ V, float* __restrict__ O,
               int win) {
    extern __shared__ float sm[];
    float (*Qs)[FP]     = (float(*)[FP])sm;
    float (*Ps)[FP]     = (float(*)[FP])(sm + 64 * FP);
    float (*Ks)[64][FP] = (float(*)[64][FP])(sm + 2 * 64 * FP);
    float (*Vs)[64][FP] = (float(*)[64][FP])(sm + 4 * 64 * FP);

    int qt  = gridDim.x - 1 - blockIdx.x;
    int h   = blockIdx.y;
    int kvh = h >> 2;
    int tid = threadIdx.x;
    int wid = tid >> 5;
    int lane = tid & 31;
    int g  = lane >> 2;
    int cq = lane & 3;
    int m0 = wid * 16;
    int q0 = qt * 64;

    int jt0 = 0;
    if (win > 0) { jt0 = qt - 4; if (jt0 < 0) jt0 = 0; }

    // issue K/V stage for first kv tile
    {
        int j0 = jt0 * 64;
        #pragma unroll
        for (int t = 0; t < 8; t++) {
            int idx = tid + t * 128;
            int jj = idx >> 4, d4 = (idx & 15) << 2;
            size_t base = (size_t)(j0 + jj) * LATD + kvh * HDIM + d4;
            cp16((uint32_t)__cvta_generic_to_shared(&Ks[0][jj][d4]), K + base);
            cp16((uint32_t)__cvta_generic_to_shared(&Vs[0][jj][d4]), V + base);
        }
        cp_commit();
    }

    // stage Q (already tf32 + scaled)
    #pragma unroll
    for (int t = 0; t < 8; t++) {
        int idx = tid + t * 128;
        int qi = idx >> 4, d4 = (idx & 15) << 2;
        *(float4*)&Qs[qi][d4] =
            *(const float4*)(Q + (size_t)(q0 + qi) * DMODEL + h * HDIM + d4);
    }
    __syncthreads();

    // hoist Q fragments (constant across kv tiles)
    uint32_t qf[8][4];
    #pragma unroll
    for (int k8 = 0; k8 < HDIM; k8 += 8) {
        qf[k8 >> 3][0] = __float_as_uint(Qs[m0 + g    ][k8 + cq    ]);
        qf[k8 >> 3][1] = __float_as_uint(Qs[m0 + g + 8][k8 + cq    ]);
        qf[k8 >> 3][2] = __float_as_uint(Qs[m0 + g    ][k8 + cq + 4]);
        qf[k8 >> 3][3] = __float_as_uint(Qs[m0 + g + 8][k8 + cq + 4]);
    }

    float o[8][4];
    #pragma unroll
    for (int u = 0; u < 8; u++)
        #pragma unroll
        for (int i = 0; i < 4; i++) o[u][i] = 0.0f;
    float mrow0 = -60.0f, mrow1 = -60.0f;
    float lrow0 = 0.0f,   lrow1 = 0.0f;

    int row0 = q0 + m0 + g;
    int row1 = row0 + 8;

    for (int jt = jt0; jt <= qt; jt++) {
        int b = (jt - jt0) & 1;
        if (jt < qt) {
            int j0 = (jt + 1) * 64;
            #pragma unroll
            for (int t = 0; t < 8; t++) {
                int idx = tid + t * 128;
                int jj = idx >> 4, d4 = (idx & 15) << 2;
                size_t base = (size_t)(j0 + jj) * LATD + kvh * HDIM + d4;
                cp16((uint32_t)__cvta_generic_to_shared(&Ks[b ^ 1][jj][d4]), K + base);
                cp16((uint32_t)__cvta_generic_to_shared(&Vs[b ^ 1][jj][d4]), V + base);
            }
            cp_commit();
            cp_wait<1>();
        } else {
            cp_wait<0>();
        }
        __syncthreads();

        int j0 = jt * 64;

        // S = Q K^T (scores pre-scaled via Q)
        float s[8][4];
        #pragma unroll
        for (int u = 0; u < 8; u++)
            #pragma unroll
            for (int i = 0; i < 4; i++) s[u][i] = 0.0f;

        #pragma unroll
        for (int k8 = 0; k8 < HDIM; k8 += 8) {
            #pragma unroll
            for (int u = 0; u < 8; u++) {
                uint32_t b0 = __float_as_uint(Ks[b][u * 8 + g][k8 + cq    ]);
                uint32_t b1 = __float_as_uint(Ks[b][u * 8 + g][k8 + cq + 4]);
                mma_tf32(s[u], qf[k8 >> 3][0], qf[k8 >> 3][1],
                         qf[k8 >> 3][2], qf[k8 >> 3][3], b0, b1);
            }
        }

        // mask
        #pragma unroll
        for (int u = 0; u < 8; u++) {
            int col = j0 + u * 8 + 2 * cq;
            #pragma unroll
            for (int i = 0; i < 4; i++) {
                int q  = (i < 2) ? row0 : row1;
                int kj = col + (i & 1);
                bool vis = (kj <= q) && (win == 0 || (q - kj) < win);
                if (!vis) s[u][i] = -1e30f;
            }
        }

        // online softmax
        float rm0 = -1e30f, rm1 = -1e30f;
        #pragma unroll
        for (int u = 0; u < 8; u++) {
            rm0 = fmaxf(rm0, fmaxf(s[u][0], s[u][1]));
            rm1 = fmaxf(rm1, fmaxf(s[u][2], s[u][3]));
        }
        #pragma unroll
        for (int off = 1; off <= 2; off <<= 1) {
            rm0 = fmaxf(rm0, __shfl_xor_sync(0xffffffffu, rm0, off));
            rm1 = fmaxf(rm1, __shfl_xor_sync(0xffffffffu, rm1, off));
        }
        float mn0 = fmaxf(mrow0, rm0);
        float mn1 = fmaxf(mrow1, rm1);
        float al0 = __expf(mrow0 - mn0);
        float al1 = __expf(mrow1 - mn1);
        float rs0 = 0.0f, rs1 = 0.0f;
        #pragma unroll
        for (int u = 0; u < 8; u++) {
            float p0 = __expf(s[u][0] - mn0);
            float p1 = __expf(s[u][1] - mn0);
            float p2 = __expf(s[u][2] - mn1);
            float p3 = __expf(s[u][3] - mn1);
            s[u][0] = p0; s[u][1] = p1; s[u][2] = p2; s[u][3] = p3;
            rs0 += p0 + p1;
            rs1 += p2 + p3;
        }
        #pragma unroll
        for (int off = 1; off <= 2; off <<= 1) {
            rs0 += __shfl_xor_sync(0xffffffffu, rs0, off);
            rs1 += __shfl_xor_sync(0xffffffffu, rs1, off);
        }
        lrow0 = lrow0 * al0 + rs0;
        lrow1 = lrow1 * al1 + rs1;
        mrow0 = mn0;
        mrow1 = mn1;
        #pragma unroll
        for (int u = 0; u < 8; u++) {
            o[u][0] *= al0; o[u][1] *= al0;
            o[u][2] *= al1; o[u][3] *= al1;
        }

        // P -> SMEM (tf32), same warp consumes
        #pragma unroll
        for (int u = 0; u < 8; u++) {
            int col = u * 8 + 2 * cq;
            *(uint2*)&Ps[m0 + g    ][col] = make_uint2(f2tf32(s[u][0]), f2tf32(s[u][1]));
            *(uint2*)&Ps[m0 + g + 8][col] = make_uint2(f2tf32(s[u][2]), f2tf32(s[u][3]));
        }
        __syncwarp();

        // O += P @ V
        #pragma unroll
        for (int k8 = 0; k8 < 64; k8 += 8) {
            uint32_t a0 = __float_as_uint(Ps[m0 + g    ][k8 + cq    ]);
            uint32_t a1 = __float_as_uint(Ps[m0 + g + 8][k8 + cq    ]);
            uint32_t a2 = __float_as_uint(Ps[m0 + g    ][k8 + cq + 4]);
            uint32_t a3 = __float_as_uint(Ps[m0 + g + 8][k8 + cq + 4]);
            #pragma unroll
            for (int u = 0; u < 8; u++) {
                uint32_t b0 = __float_as_uint(Vs[b][k8 + cq    ][u * 8 + g]);
                uint32_t b1 = __float_as_uint(Vs[b][k8 + cq + 4][u * 8 + g]);
                mma_tf32(o[u], a0, a1, a2, a3, b0, b1);
            }
        }
        __syncthreads();
    }

    float inv0 = 1.0f / lrow0;
    float inv1 = 1.0f / lrow1;
    #pragma unroll
    for (int u = 0; u < 8; u++) {
        int col = u * 8 + 2 * cq;
        *(float2*)(O + (size_t)row0 * DMODEL + h * HDIM + col) =
            make_float2(tf32f(o[u][0] * inv0), tf32f(o[u][1] * inv0));
        *(float2*)(O + (size_t)row1 * DMODEL + h * HDIM + col) =
            make_float2(tf32f(o[u][2] * inv1), tf32f(o[u][3] * inv1));
    }
}

// ---------------------------------------------------------------------------
// Launch
// ---------------------------------------------------------------------------
extern "C" void kernel_launch(void* const* d_in, const int* in_sizes, int n_in,
                              void* d_out, int out_size) {
    (void)in_sizes; (void)n_in; (void)out_size;

    const float* hidden   = (const float*)d_in[0];
    const float* norm1_w  = (const float*)d_in[1];
    const float* norm2_w  = (const float*)d_in[2];
    const float* w_g_wq   = (const float*)d_in[3];
    const float* w_g_kvdn = (const float*)d_in[4];
    const float* w_g_k_up = (const float*)d_in[5];
    const float* w_g_v_up = (const float*)d_in[6];
    const float* w_g_wo   = (const float*)d_in[7];
    const float* w_l_wq   = (const float*)d_in[8];
    const float* w_l_wk   = (const float*)d_in[9];
    const float* w_l_wv   = (const float*)d_in[10];
    const float* w_l_wo   = (const float*)d_in[11];
    float* out = (float*)d_out;

    float *x1, *q, *lat, *k, *v, *attn, *gw;
    cudaGetSymbolAddress((void**)&x1,   g_x1);
    cudaGetSymbolAddress((void**)&q,    g_q);
    cudaGetSymbolAddress((void**)&lat,  g_lat);
    cudaGetSymbolAddress((void**)&k,    g_k);
    cudaGetSymbolAddress((void**)&v,    g_v);
    cudaGetSymbolAddress((void**)&attn, g_attn);
    cudaGetSymbolAddress((void**)&gw,   g_w);

    const int GEMM128_SMEM = (2 * 128 * 36 + 2 * 32 * 68) * sizeof(float);
    const int GEMM64_SMEM  = (2 * 64 * 36 + 2 * 32 * 68) * sizeof(float);
    const int ATTN_SMEM    = 6 * 64 * FP * sizeof(float);

    cudaFuncSetAttribute(mma_gemm<128, 64, 32>,
                         cudaFuncAttributeMaxDynamicSharedMemorySize, GEMM128_SMEM);
    cudaFuncSetAttribute(mma_gemm<64, 64, 32>,
                         cudaFuncAttributeMaxDynamicSharedMemorySize, GEMM64_SMEM);
    cudaFuncSetAttribute(fattn_mma,
                         cudaFuncAttributeMaxDynamicSharedMemorySize, ATTN_SMEM);

    dim3 gridAttn(SEQ / 64, NH);

    // ---- Pre-round all weights to tf32 (once per call) ----
    round_tf32_5<<<2432, 256>>>((float4*)(gw + GWQ),
        (const float4*)w_g_wq,   262144,
        (const float4*)w_g_kvdn,  65536,
        (const float4*)w_g_k_up,  16384,
        (const float4*)w_g_v_up,  16384,
        (const float4*)w_g_wo,   262144);
    round_tf32_5<<<2560, 256>>>((float4*)(gw + LWQ),
        (const float4*)w_l_wq,   262144,
        (const float4*)w_l_wk,    65536,
        (const float4*)w_l_wv,    65536,
        (const float4*)w_l_wo,   262144,
        (const float4*)w_l_wo,        0);

    // ---- Layer 1: global latent attention ----
    rmsnorm_kernel<<<SEQ, 256>>>(hidden, norm1_w, x1);
    mma_gemm<128, 64, 32><<<dim3(20, 16), 256, GEMM128_SMEM>>>(
        x1, gw + GWQ, q, DMODEL, gw + GKV, lat, LATD,
        nullptr, nullptr, 0, nullptr, DMODEL, /*rflags=*/2);
    mma_gemm<64, 64, 32><<<dim3(8, 32), 256, GEMM64_SMEM>>>(
        lat, gw + GKUP, k, LATD, gw + GVUP, v, LATD,
        nullptr, nullptr, 0, nullptr, LATD, /*rflags=*/2);
    rope_qknorm_fast<<<SEQ, 640>>>(q, k, 1000000.0f);
    fattn_mma<<<gridAttn, 128, ATTN_SMEM>>>(q, k, v, attn, /*win=*/0);
    mma_gemm<128, 64, 32><<<dim3(16, 16), 256, GEMM128_SMEM>>>(
        attn, gw + GWO, out, DMODEL, nullptr, nullptr, 0,
        nullptr, nullptr, 0, hidden, DMODEL, /*rflags=*/0);

    // ---- Layer 2: local GQA attention ----
    rmsnorm_kernel<<<SEQ, 256>>>(out, norm2_w, x1);
    mma_gemm<128, 64, 32><<<dim3(24, 16), 256, GEMM128_SMEM>>>(
        x1, gw + LWQ, q, DMODEL, gw + LWK, k, LATD,
        gw + LWV, v, LATD, nullptr, DMODEL, /*rflags=*/4);
    rope_qknorm_fast<<<SEQ, 640>>>(q, k, 10000.0f);
    fattn_mma<<<gridAttn, 128, ATTN_SMEM>>>(q, k, v, attn, /*win=*/WINSZ);
    mma_gemm<128, 64, 32><<<dim3(16, 16), 256, GEMM128_SMEM>>>(
        attn, gw + LWO, out, DMODEL, nullptr, nullptr, 0,
        nullptr, nullptr, 0, out, DMODEL, /*rflags=*/0);
}

// round 11
// speedup vs baseline: 15.1410x; 1.6323x over previous
#include <cuda_runtime.h>
#include <math.h>
#include <stdint.h>

#define SEQ    2048
#define DMODEL 1024
#define NH     16
#define NKVH   4
#define HDIM   64
#define LATD   256
#define WINSZ  256

// ---------------------------------------------------------------------------
// Scratch (device globals; no allocation allowed). Activations in bf16.
// ---------------------------------------------------------------------------
__device__ uint16_t g_x1  [SEQ * DMODEL];
__device__ uint16_t g_q   [SEQ * DMODEL];
__device__ uint16_t g_lat [SEQ * LATD];
__device__ uint16_t g_k   [SEQ * LATD];
__device__ uint16_t g_v   [SEQ * LATD];
__device__ uint16_t g_vT  [LATD * SEQ];     // V transposed [hd][seq]
__device__ uint16_t g_attn[SEQ * DMODEL];

// bf16 weights, TRANSPOSED to [N][K], concatenated (element offsets)
#define GWQ  0
#define GKV  1048576
#define GKUP 1310720
#define GVUP 1376256
#define GWO  1441792
#define LWQ  2490368
#define LWK  3538944
#define LWV  3801088
#define LWO  4063232
__device__ uint16_t g_w[5111808];

// ---------------------------------------------------------------------------
// Helpers
// ---------------------------------------------------------------------------
__device__ __forceinline__ uint16_t f2bf(float x) {
    uint16_t r;
    asm("cvt.rn.bf16.f32 %0, %1;" : "=h"(r) : "f"(x));
    return r;
}
__device__ __forceinline__ uint32_t pack_bf16(float lo, float hi) {
    uint32_t d;
    asm("cvt.rn.bf16x2.f32 %0, %1, %2;" : "=r"(d) : "f"(hi), "f"(lo));
    return d;
}
__device__ __forceinline__ float bf_lo(uint32_t w) {
    return __uint_as_float(w << 16);
}
__device__ __forceinline__ float bf_hi(uint32_t w) {
    return __uint_as_float(w & 0xffff0000u);
}

__device__ __forceinline__ void mma_bf16(float* c,
                                         uint32_t a0, uint32_t a1,
                                         uint32_t a2, uint32_t a3,
                                         uint32_t b0, uint32_t b1) {
    asm volatile(
        "mma.sync.aligned.m16n8k16.row.col.f32.bf16.bf16.f32 "
        "{%0,%1,%2,%3}, {%4,%5,%6,%7}, {%8,%9}, {%0,%1,%2,%3};\n"
        : "+f"(c[0]), "+f"(c[1]), "+f"(c[2]), "+f"(c[3])
        : "r"(a0), "r"(a1), "r"(a2), "r"(a3), "r"(b0), "r"(b1));
}

__device__ __forceinline__ void cp16(uint32_t s, const void* g) {
    asm volatile("cp.async.cg.shared.global [%0], [%1], 16;\n"
                 :: "r"(s), "l"(g));
}
__device__ __forceinline__ void cp_commit() {
    asm volatile("cp.async.commit_group;\n");
}
template<int N>
__device__ __forceinline__ void cp_wait() {
    asm volatile("cp.async.wait_group %0;\n" :: "n"(N));
}

// ---------------------------------------------------------------------------
// Weight transpose + bf16 convert: dst[n][k] = bf16(src[k][n])
// Block (32, 8), grid (N/32, K/32).
// ---------------------------------------------------------------------------
__global__ void transpose_w(uint16_t* __restrict__ dst,
                            const float* __restrict__ src, int K, int N) {
    __shared__ float t[32][33];
    int n0 = blockIdx.x * 32, k0 = blockIdx.y * 32;
    int x = threadIdx.x, y = threadIdx.y;
    #pragma unroll
    for (int i = 0; i < 32; i += 8)
        t[y + i][x] = src[(size_t)(k0 + y + i) * N + n0 + x];
    __syncthreads();
    #pragma unroll
    for (int i = 0; i < 32; i += 8)
        dst[(size_t)(n0 + y + i) * K + k0 + x] = f2bf(t[x][y + i]);
}

// V transpose (bf16 -> bf16): dst[hd][s] = src[s][hd]
__global__ void transpose_v(uint16_t* __restrict__ dst,
                            const uint16_t* __restrict__ src) {
    __shared__ uint16_t t[32][33];
    int h0 = blockIdx.x * 32, s0 = blockIdx.y * 32;
    int x = threadIdx.x, y = threadIdx.y;
    #pragma unroll
    for (int i = 0; i < 32; i += 8)
        t[y + i][x] = src[(size_t)(s0 + y + i) * LATD + h0 + x];
    __syncthreads();
    #pragma unroll
    for (int i = 0; i < 32; i += 8)
        dst[(size_t)(h0 + y + i) * SEQ + s0 + x] = t[x][y + i];
}

// ---------------------------------------------------------------------------
// RMSNorm: fp32 in -> bf16 out
// ---------------------------------------------------------------------------
__global__ void rmsnorm_kernel(const float* __restrict__ x,
                               const float* __restrict__ w,
                               uint16_t* __restrict__ y) {
    int row = blockIdx.x;
    int tid = threadIdx.x;
    const float4* xr = (const float4*)(x + (size_t)row * DMODEL);
    float4 v = xr[tid];
    float ss = v.x * v.x + v.y * v.y + v.z * v.z + v.w * v.w;
    __shared__ float red[256];
    red[tid] = ss;
    __syncthreads();
    #pragma unroll
    for (int o = 128; o > 0; o >>= 1) {
        if (tid < o) red[tid] += red[tid + o];
        __syncthreads();
    }
    float r = rsqrtf(red[0] / (float)DMODEL + 1e-6f);
    float4 wv = ((const float4*)w)[tid];
    uint32_t* yw = (uint32_t*)(y + (size_t)row * DMODEL);
    yw[2 * tid]     = pack_bf16(v.x * r * wv.x, v.y * r * wv.y);
    yw[2 * tid + 1] = pack_bf16(v.z * r * wv.z, v.w * r * wv.w);
}

// ---------------------------------------------------------------------------
// Segmented BF16 GEMM, cp.async 2-stage pipeline, mma m16n8k16.
// A bf16 [M][K]; B bf16 TRANSPOSED [nseg][K]; C per segment either
// bf16 [M][nseg] (bfout bit set) or fp32 (+R residual).
// 256 threads = 8 warps (4 m x 2 n).
// ---------------------------------------------------------------------------
template<int BM, int BN, int BK>
__global__ __launch_bounds__(256)
void bgemm(const uint16_t* __restrict__ A,
           const uint16_t* __restrict__ B0, void* C0, int n0,
           const uint16_t* __restrict__ B1, void* C1, int n1,
           const uint16_t* __restrict__ B2, void* C2, int n2,
           const float* __restrict__ R, int K, int bfout) {
    constexpr int PW  = BK / 2 + 4;       // word pitch (16 data + 4 pad)
    constexpr int WM  = BM / 4;
    constexpr int WN  = BN / 2;
    constexpr int MT  = WM / 16;
    constexpr int NT  = WN / 8;
    constexpr int ACP = BM * 4 / 256;     // cp16 per thread per stage (A)
    constexpr int BCP = BN * 4 / 256;

    extern __shared__ uint32_t smw[];
    uint32_t (*As)[BM][PW] = (uint32_t(*)[BM][PW])smw;
    uint32_t (*Bs)[BN][PW] = (uint32_t(*)[BN][PW])(smw + 2 * BM * PW);

    int tid  = threadIdx.x;
    int wid  = tid >> 5;
    int lane = tid & 31;
    int g    = lane >> 2;
    int cq   = lane & 3;
    int wm   = (wid >> 1) * WM;
    int wn   = (wid & 1) * WN;
    int r0   = blockIdx.y * BM;
    int c0   = blockIdx.x * BN;

    const uint16_t* Bseg;
    void* Cseg;
    int nseg, segc, segi;
    if (c0 < n0)           { Bseg = B0; Cseg = C0; nseg = n0; segc = c0; segi = 0; }
    else if (c0 < n0 + n1) { Bseg = B1; Cseg = C1; nseg = n1; segc = c0 - n0; segi = 1; }
    else                   { Bseg = B2; Cseg = C2; nseg = n2; segc = c0 - n0 - n1; segi = 2; }
    bool bfo = (bfout >> segi) & 1;

    float acc[MT][NT][4];
    #pragma unroll
    for (int t = 0; t < MT; t++)
        #pragma unroll
        for (int u = 0; u < NT; u++)
            #pragma unroll
            for (int i = 0; i < 4; i++) acc[t][u][i] = 0.0f;

    // stage 0
    #pragma unroll
    for (int t = 0; t < ACP; t++) {
        int idx = tid + t * 256;
        int ar = idx >> 2, ch = idx & 3;
        cp16((uint32_t)__cvta_generic_to_shared(&As[0][ar][ch * 4]),
             A + (size_t)(r0 + ar) * K + ch * 8);
    }
    #pragma unroll
    for (int t = 0; t < BCP; t++) {
        int idx = tid + t * 256;
        int br = idx >> 2, ch = idx & 3;
        cp16((uint32_t)__cvta_generic_to_shared(&Bs[0][br][ch * 4]),
             Bseg + (size_t)(segc + br) * K + ch * 8);
    }
    cp_commit();

    int NKB = K / BK;
    for (int kb = 0; kb < NKB; kb++) {
        int b = kb & 1;
        if (kb + 1 < NKB) {
            int k0 = (kb + 1) * BK;
            #pragma unroll
            for (int t = 0; t < ACP; t++) {
                int idx = tid + t * 256;
                int ar = idx >> 2, ch = idx & 3;
                cp16((uint32_t)__cvta_generic_to_shared(&As[b ^ 1][ar][ch * 4]),
                     A + (size_t)(r0 + ar) * K + k0 + ch * 8);
            }
            #pragma unroll
            for (int t = 0; t < BCP; t++) {
                int idx = tid + t * 256;
                int br = idx >> 2, ch = idx & 3;
                cp16((uint32_t)__cvta_generic_to_shared(&Bs[b ^ 1][br][ch * 4]),
                     Bseg + (size_t)(segc + br) * K + k0 + ch * 8);
            }
            cp_commit();
            cp_wait<1>();
        } else {
            cp_wait<0>();
        }
        __syncthreads();

        #pragma unroll
        for (int k16 = 0; k16 < BK / 16; k16++) {
            int kw = k16 * 8;
            uint32_t af[MT][4];
            #pragma unroll
            for (int t = 0; t < MT; t++) {
                int m0 = wm + 16 * t + g;
                af[t][0] = As[b][m0    ][kw + cq    ];
                af[t][1] = As[b][m0 + 8][kw + cq    ];
                af[t][2] = As[b][m0    ][kw + cq + 4];
                af[t][3] = As[b][m0 + 8][kw + cq + 4];
            }
            uint32_t bf[NT][2];
            #pragma unroll
            for (int u = 0; u < NT; u++) {
                int nn = wn + 8 * u + g;
                bf[u][0] = Bs[b][nn][kw + cq    ];
                bf[u][1] = Bs[b][nn][kw + cq + 4];
            }
            #pragma unroll
            for (int t = 0; t < MT; t++)
                #pragma unroll
                for (int u = 0; u < NT; u++)
                    mma_bf16(acc[t][u], af[t][0], af[t][1], af[t][2], af[t][3],
                             bf[u][0], bf[u][1]);
        }
        __syncthreads();
    }

    #pragma unroll
    for (int t = 0; t < MT; t++) {
        int row = r0 + wm + 16 * t + g;
        #pragma unroll
        for (int u = 0; u < NT; u++) {
            int col = segc + wn + 8 * u + 2 * cq;
            size_t off0 = (size_t)row * nseg + col;
            size_t off1 = (size_t)(row + 8) * nseg + col;
            if (bfo) {
                uint16_t* Cb = (uint16_t*)Cseg;
                *(uint32_t*)(Cb + off0) = pack_bf16(acc[t][u][0], acc[t][u][1]);
                *(uint32_t*)(Cb + off1) = pack_bf16(acc[t][u][2], acc[t][u][3]);
            } else {
                float* Cf = (float*)Cseg;
                float2 r0v = make_float2(0.f, 0.f), r1v = make_float2(0.f, 0.f);
                if (R) {
                    r0v = *(const float2*)(R + off0);
                    r1v = *(const float2*)(R + off1);
                }
                *(float2*)(Cf + off0) = make_float2(acc[t][u][0] + r0v.x,
                                                    acc[t][u][1] + r0v.y);
                *(float2*)(Cf + off1) = make_float2(acc[t][u][2] + r1v.x,
                                                    acc[t][u][3] + r1v.y);
            }
        }
    }
}

// ---------------------------------------------------------------------------
// Fast RoPE + qk_norm on bf16 q/k: one block per s, 20 warps = 20 heads.
// Q additionally scaled by 1/8 (exact pow2; folded softmax scale).
// ---------------------------------------------------------------------------
__global__ __launch_bounds__(640)
void rope_qknorm_fast(uint16_t* __restrict__ q, uint16_t* __restrict__ k,
                      float base) {
    __shared__ float scs[32], ssn[32];
    int s   = blockIdx.x;
    int tid = threadIdx.x;
    int w   = tid >> 5;
    int i   = tid & 31;

    if (tid < 32) {
        float invf = powf(base, -((float)(2 * tid) / (float)HDIM));
        float ang = (float)s * invf;
        sincosf(ang, &ssn[tid], &scs[tid]);
    }
    __syncthreads();

    uint32_t* p;
    float scale;
    if (w < NH) { p = (uint32_t*)(q + (size_t)s * DMODEL + w * HDIM); scale = 0.125f; }
    else        { p = (uint32_t*)(k + (size_t)s * LATD + (w - NH) * HDIM); scale = 1.0f; }

    uint32_t xw = p[i];
    float xe = bf_lo(xw), xo = bf_hi(xw);
    float cs = scs[i], sn = ssn[i];
    float re = xe * cs - xo * sn;
    float ro = xe * sn + xo * cs;

    float ss = re * re + ro * ro;
    #pragma unroll
    for (int o = 16; o > 0; o >>= 1)
        ss += __shfl_xor_sync(0xffffffffu, ss, o);

    float r = rsqrtf(ss / (float)HDIM + 1e-6f) * scale;
    p[i] = pack_bf16(re * r, ro * r);
}

// ---------------------------------------------------------------------------
// BF16 mma flash attention, cp.async double-buffered K/V(T), hoisted Q frags.
// Block = (64-query tile, head), 128 threads / 4 warps.
// SMEM words (pitch 36): Qs[64] Ps[64] Ks[2][64] Vt[2][64]  = 55296 B
// ---------------------------------------------------------------------------
#define APW 36
__global__ __launch_bounds__(128)
void fattn_mma(const uint16_t* __restrict__ Q, const uint16_t* __restrict__ K,
               const uint16_t* __restrict__ VT, uint16_t* __restrict__ O,
               int win) {
    extern __shared__ uint32_t smw[];
    uint32_t (*Qs)[APW]     = (uint32_t(*)[APW])smw;
    uint32_t (*Ps)[APW]     = (uint32_t(*)[APW])(smw + 64 * APW);
    uint32_t (*Ks)[64][APW] = (uint32_t(*)[64][APW])(smw + 2 * 64 * APW);
    uint32_t (*Vt)[64][APW] = (uint32_t(*)[64][APW])(smw + 4 * 64 * APW);

    int qt  = gridDim.x - 1 - blockIdx.x;   // heavy tiles first
    int h   = blockIdx.y;
    int kvh = h >> 2;
    int tid = threadIdx.x;
    int wid = tid >> 5;
    int lane = tid & 31;
    int g  = lane >> 2;
    int cq = lane & 3;
    int m0 = wid * 16;
    int q0 = qt * 64;

    int jt0 = 0;
    if (win > 0) { jt0 = qt - 4; if (jt0 < 0) jt0 = 0; }

    // stage first K tile + V^T tile
    {
        int j0 = jt0 * 64;
        #pragma unroll
        for (int t = 0; t < 4; t++) {
            int idx = tid + t * 128;
            int jj = idx >> 3, ch = idx & 7;
            cp16((uint32_t)__cvta_generic_to_shared(&Ks[0][jj][ch * 4]),
                 K + (size_t)(j0 + jj) * LATD + kvh * HDIM + ch * 8);
            cp16((uint32_t)__cvta_generic_to_shared(&Vt[0][jj][ch * 4]),
                 VT + (size_t)(kvh * HDIM + jj) * SEQ + j0 + ch * 8);
        }
        cp_commit();
    }

    // stage Q (bf16, pre-scaled)
    #pragma unroll
    for (int t = 0; t < 4; t++) {
        int idx = tid + t * 128;
        int qi = idx >> 3, ch = idx & 7;
        *(uint4*)&Qs[qi][ch * 4] =
            *(const uint4*)(Q + (size_t)(q0 + qi) * DMODEL + h * HDIM + ch * 8);
    }
    __syncthreads();

    // hoist Q fragments (4 k16 windows over HDIM=64)
    uint32_t qf[4][4];
    #pragma unroll
    for (int k16 = 0; k16 < 4; k16++) {
        int kw = k16 * 8;
        qf[k16][0] = Qs[m0 + g    ][kw + cq    ];
        qf[k16][1] = Qs[m0 + g + 8][kw + cq    ];
        qf[k16][2] = Qs[m0 + g    ][kw + cq + 4];
        qf[k16][3] = Qs[m0 + g + 8][kw + cq + 4];
    }

    float o[8][4];
    #pragma unroll
    for (int u = 0; u < 8; u++)
        #pragma unroll
        for (int i = 0; i < 4; i++) o[u][i] = 0.0f;
    float mrow0 = -60.0f, mrow1 = -60.0f;
    float lrow0 = 0.0f,   lrow1 = 0.0f;

    int row0 = q0 + m0 + g;
    int row1 = row0 + 8;

    for (int jt = jt0; jt <= qt; jt++) {
        int b = (jt - jt0) & 1;
        if (jt < qt) {
            int j0 = (jt + 1) * 64;
            #pragma unroll
            for (int t = 0; t < 4; t++) {
                int idx = tid + t * 128;
                int jj = idx >> 3, ch = idx & 7;
                cp16((uint32_t)__cvta_generic_to_shared(&Ks[b ^ 1][jj][ch * 4]),
                     K + (size_t)(j0 + jj) * LATD + kvh * HDIM + ch * 8);
                cp16((uint32_t)__cvta_generic_to_shared(&Vt[b ^ 1][jj][ch * 4]),
                     VT + (size_t)(kvh * HDIM + jj) * SEQ + j0 + ch * 8);
            }
            cp_commit();
            cp_wait<1>();
        } else {
            cp_wait<0>();
        }
        __syncthreads();

        int j0 = jt * 64;

        // S = Q K^T
        float s[8][4];
        #pragma unroll
        for (int u = 0; u < 8; u++)
            #pragma unroll
            for (int i = 0; i < 4; i++) s[u][i] = 0.0f;

        #pragma unroll
        for (int k16 = 0; k16 < 4; k16++) {
            int kw = k16 * 8;
            #pragma unroll
            for (int u = 0; u < 8; u++) {
                uint32_t b0 = Ks[b][u * 8 + g][kw + cq    ];
                uint32_t b1 = Ks[b][u * 8 + g][kw + cq + 4];
                mma_bf16(s[u], qf[k16][0], qf[k16][1], qf[k16][2], qf[k16][3],
                         b0, b1);
            }
        }

        // mask
        #pragma unroll
        for (int u = 0; u < 8; u++) {
            int col = j0 + u * 8 + 2 * cq;
            #pragma unroll
            for (int i = 0; i < 4; i++) {
                int q  = (i < 2) ? row0 : row1;
                int kj = col + (i & 1);
                bool vis = (kj <= q) && (win == 0 || (q - kj) < win);
                if (!vis) s[u][i] = -1e30f;
            }
        }

        // online softmax
        float rm0 = -1e30f, rm1 = -1e30f;
        #pragma unroll
        for (int u = 0; u < 8; u++) {
            rm0 = fmaxf(rm0, fmaxf(s[u][0], s[u][1]));
            rm1 = fmaxf(rm1, fmaxf(s[u][2], s[u][3]));
        }
        #pragma unroll
        for (int off = 1; off <= 2; off <<= 1) {
            rm0 = fmaxf(rm0, __shfl_xor_sync(0xffffffffu, rm0, off));
            rm1 = fmaxf(rm1, __shfl_xor_sync(0xffffffffu, rm1, off));
        }
        float mn0 = fmaxf(mrow0, rm0);
        float mn1 = fmaxf(mrow1, rm1);
        float al0 = __expf(mrow0 - mn0);
        float al1 = __expf(mrow1 - mn1);
        float rs0 = 0.0f, rs1 = 0.0f;
        #pragma unroll
        for (int u = 0; u < 8; u++) {
            float p0 = __expf(s[u][0] - mn0);
            float p1 = __expf(s[u][1] - mn0);
            float p2 = __expf(s[u][2] - mn1);
            float p3 = __expf(s[u][3] - mn1);
            s[u][0] = p0; s[u][1] = p1; s[u][2] = p2; s[u][3] = p3;
            rs0 += p0 + p1;
            rs1 += p2 + p3;
        }
        #pragma unroll
        for (int off = 1; off <= 2; off <<= 1) {
            rs0 += __shfl_xor_sync(0xffffffffu, rs0, off);
            rs1 += __shfl_xor_sync(0xffffffffu, rs1, off);
        }
        lrow0 = lrow0 * al0 + rs0;
        lrow1 = lrow1 * al1 + rs1;
        mrow0 = mn0;
        mrow1 = mn1;
        #pragma unroll
        for (int u = 0; u < 8; u++) {
            o[u][0] *= al0; o[u][1] *= al0;
            o[u][2] *= al1; o[u][3] *= al1;
        }

        // P -> SMEM as bf16x2 (packed along key), same warp consumes
        #pragma unroll
        for (int u = 0; u < 8; u++) {
            Ps[m0 + g    ][u * 4 + cq] = pack_bf16(s[u][0], s[u][1]);
            Ps[m0 + g + 8][u * 4 + cq] = pack_bf16(s[u][2], s[u][3]);
        }
        __syncwarp();

        // O += P @ V  (B from V^T: [hd][key])
        #pragma unroll
        for (int k16 = 0; k16 < 4; k16++) {
            int kw = k16 * 8;
            uint32_t a0 = Ps[m0 + g    ][kw + cq    ];
            uint32_t a1 = Ps[m0 + g + 8][kw + cq    ];
            uint32_t a2 = Ps[m0 + g    ][kw + cq + 4];
            uint32_t a3 = Ps[m0 + g + 8][kw + cq + 4];
            #pragma unroll
            for (int u = 0; u < 8; u++) {
                uint32_t b0 = Vt[b][u * 8 + g][kw + cq    ];
                uint32_t b1 = Vt[b][u * 8 + g][kw + cq + 4];
                mma_bf16(o[u], a0, a1, a2, a3, b0, b1);
            }
        }
        __syncthreads();
    }

    float inv0 = 1.0f / lrow0;
    float inv1 = 1.0f / lrow1;
    #pragma unroll
    for (int u = 0; u < 8; u++) {
        int col = u * 8 + 2 * cq;
        *(uint32_t*)(O + (size_t)row0 * DMODEL + h * HDIM + col) =
            pack_bf16(o[u][0] * inv0, o[u][1] * inv0);
        *(uint32_t*)(O + (size_t)row1 * DMODEL + h * HDIM + col) =
            pack_bf16(o[u][2] * inv1, o[u][3] * inv1);
    }
}

// ---------------------------------------------------------------------------
// Launch
// ---------------------------------------------------------------------------
extern "C" void kernel_launch(void* const* d_in, const int* in_sizes, int n_in,
                              void* d_out, int out_size) {
    (void)in_sizes; (void)n_in; (void)out_size;

    const float* hidden   = (const float*)d_in[0];
    const float* norm1_w  = (const float*)d_in[1];
    const float* norm2_w  = (const float*)d_in[2];
    const float* w_g_wq   = (const float*)d_in[3];
    const float* w_g_kvdn = (const float*)d_in[4];
    const float* w_g_k_up = (const float*)d_in[5];
    const float* w_g_v_up = (const float*)d_in[6];
    const float* w_g_wo   = (const float*)d_in[7];
    const float* w_l_wq   = (const float*)d_in[8];
    const float* w_l_wk   = (const float*)d_in[9];
    const float* w_l_wv   = (const float*)d_in[10];
    const float* w_l_wo   = (const float*)d_in[11];
    float* out = (float*)d_out;

    uint16_t *x1, *q, *lat, *k, *v, *vT, *attn, *gw;
    cudaGetSymbolAddress((void**)&x1,   g_x1);
    cudaGetSymbolAddress((void**)&q,    g_q);
    cudaGetSymbolAddress((void**)&lat,  g_lat);
    cudaGetSymbolAddress((void**)&k,    g_k);
    cudaGetSymbolAddress((void**)&v,    g_v);
    cudaGetSymbolAddress((void**)&vT,   g_vT);
    cudaGetSymbolAddress((void**)&attn, g_attn);
    cudaGetSymbolAddress((void**)&gw,   g_w);

    const int GEMM128_SMEM = (2 * 128 * 20 + 2 * 64 * 20) * 4;  // 30720
    const int GEMM64_SMEM  = (2 * 64 * 20 + 2 * 64 * 20) * 4;   // 20480
    const int ATTN_SMEM    = 6 * 64 * APW * 4;                  // 55296

    cudaFuncSetAttribute(bgemm<128, 64, 32>,
                         cudaFuncAttributeMaxDynamicSharedMemorySize, GEMM128_SMEM);
    cudaFuncSetAttribute(bgemm<64, 64, 32>,
                         cudaFuncAttributeMaxDynamicSharedMemorySize, GEMM64_SMEM);
    cudaFuncSetAttribute(fattn_mma,
                         cudaFuncAttributeMaxDynamicSharedMemorySize, ATTN_SMEM);

    dim3 tb(32, 8);
    dim3 gridAttn(SEQ / 64, NH);
    dim3 gridVT(LATD / 32, SEQ / 32);

    // ---- Pre-pass: transpose + bf16-convert all weights ----
    transpose_w<<<dim3(32, 32), tb>>>(gw + GWQ,  w_g_wq,   DMODEL, DMODEL);
    transpose_w<<<dim3( 8, 32), tb>>>(gw + GKV,  w_g_kvdn, DMODEL, LATD);
    transpose_w<<<dim3( 8,  8), tb>>>(gw + GKUP, w_g_k_up, LATD,   LATD);
    transpose_w<<<dim3( 8,  8), tb>>>(gw + GVUP, w_g_v_up, LATD,   LATD);
    transpose_w<<<dim3(32, 32), tb>>>(gw + GWO,  w_g_wo,   DMODEL, DMODEL);
    transpose_w<<<dim3(32, 32), tb>>>(gw + LWQ,  w_l_wq,   DMODEL, DMODEL);
    transpose_w<<<dim3( 8, 32), tb>>>(gw + LWK,  w_l_wk,   DMODEL, LATD);
    transpose_w<<<dim3( 8, 32), tb>>>(gw + LWV,  w_l_wv,   DMODEL, LATD);
    transpose_w<<<dim3(32, 32), tb>>>(gw + LWO,  w_l_wo,   DMODEL, DMODEL);

    // ---- Layer 1: global latent attention ----
    rmsnorm_kernel<<<SEQ, 256>>>(hidden, norm1_w, x1);
    bgemm<128, 64, 32><<<dim3(20, 16), 256, GEMM128_SMEM>>>(
        x1, gw + GWQ, q, DMODEL, gw + GKV, lat, LATD,
        nullptr, nullptr, 0, nullptr, DMODEL, /*bfout=*/3);
    bgemm<64, 64, 32><<<dim3(8, 32), 256, GEMM64_SMEM>>>(
        lat, gw + GKUP, k, LATD, gw + GVUP, v, LATD,
        nullptr, nullptr, 0, nullptr, LATD, /*bfout=*/3);
    transpose_v<<<gridVT, tb>>>(vT, v);
    rope_qknorm_fast<<<SEQ, 640>>>(q, k, 1000000.0f);
    fattn_mma<<<gridAttn, 128, ATTN_SMEM>>>(q, k, vT, attn, /*win=*/0);
    bgemm<128, 64, 32><<<dim3(16, 16), 256, GEMM128_SMEM>>>(
        attn, gw + GWO, out, DMODEL, nullptr, nullptr, 0,
        nullptr, nullptr, 0, hidden, DMODEL, /*bfout=*/0);

    // ---- Layer 2: local GQA attention ----
    rmsnorm_kernel<<<SEQ, 256>>>(out, norm2_w, x1);
    bgemm<128, 64, 32><<<dim3(24, 16), 256, GEMM128_SMEM>>>(
        x1, gw + LWQ, q, DMODEL, gw + LWK, k, LATD,
        gw + LWV, v, LATD, nullptr, DMODEL, /*bfout=*/7);
    transpose_v<<<gridVT, tb>>>(vT, v);
    rope_qknorm_fast<<<SEQ, 640>>>(q, k, 10000.0f);
    fattn_mma<<<gridAttn, 128, ATTN_SMEM>>>(q, k, vT, attn, /*win=*/WINSZ);
    bgemm<128, 64, 32><<<dim3(16, 16), 256, GEMM128_SMEM>>>(
        attn, gw + LWO, out, DMODEL, nullptr, nullptr, 0,
        nullptr, nullptr, 0, out, DMODEL, /*bfout=*/0);
}

// round 12
// speedup vs baseline: 16.0743x; 1.0616x over previous
#include <cuda_runtime.h>
#include <math.h>
#include <stdint.h>

#define SEQ    2048
#define DMODEL 1024
#define NH     16
#define NKVH   4
#define HDIM   64
#define LATD   256
#define WINSZ  256

// ---------------------------------------------------------------------------
// Scratch (device globals; no allocation allowed). Activations in bf16.
// ---------------------------------------------------------------------------
__device__ uint16_t g_x1  [SEQ * DMODEL];
__device__ uint16_t g_q   [SEQ * DMODEL];
__device__ uint16_t g_lat [SEQ * LATD];
__device__ uint16_t g_k   [SEQ * LATD];
__device__ uint16_t g_v   [SEQ * LATD];
__device__ uint16_t g_attn[SEQ * DMODEL];

// bf16 weights, TRANSPOSED to [N][K], concatenated (element offsets)
#define GWQ  0
#define GKV  1048576
#define GKUP 1310720
#define GVUP 1376256
#define GWO  1441792
#define LWQ  2490368
#define LWK  3538944
#define LWV  3801088
#define LWO  4063232
__device__ uint16_t g_w[5111808];

// ---------------------------------------------------------------------------
// Helpers
// ---------------------------------------------------------------------------
__device__ __forceinline__ uint16_t f2bf(float x) {
    uint16_t r;
    asm("cvt.rn.bf16.f32 %0, %1;" : "=h"(r) : "f"(x));
    return r;
}
__device__ __forceinline__ uint32_t pack_bf16(float lo, float hi) {
    uint32_t d;
    asm("cvt.rn.bf16x2.f32 %0, %1, %2;" : "=r"(d) : "f"(hi), "f"(lo));
    return d;
}
__device__ __forceinline__ float bf_lo(uint32_t w) { return __uint_as_float(w << 16); }
__device__ __forceinline__ float bf_hi(uint32_t w) { return __uint_as_float(w & 0xffff0000u); }

__device__ __forceinline__ void mma_bf16(float* c,
                                         uint32_t a0, uint32_t a1,
                                         uint32_t a2, uint32_t a3,
                                         uint32_t b0, uint32_t b1) {
    asm volatile(
        "mma.sync.aligned.m16n8k16.row.col.f32.bf16.bf16.f32 "
        "{%0,%1,%2,%3}, {%4,%5,%6,%7}, {%8,%9}, {%0,%1,%2,%3};\n"
        : "+f"(c[0]), "+f"(c[1]), "+f"(c[2]), "+f"(c[3])
        : "r"(a0), "r"(a1), "r"(a2), "r"(a3), "r"(b0), "r"(b1));
}

__device__ __forceinline__ void cp16(uint32_t s, const void* g) {
    asm volatile("cp.async.cg.shared.global [%0], [%1], 16;\n" :: "r"(s), "l"(g));
}
__device__ __forceinline__ void cp_commit() {
    asm volatile("cp.async.commit_group;\n");
}
template<int N>
__device__ __forceinline__ void cp_wait() {
    asm volatile("cp.async.wait_group %0;\n" :: "n"(N));
}
__device__ __forceinline__ uint32_t s2u(const void* p) {
    return (uint32_t)__cvta_generic_to_shared(p);
}
__device__ __forceinline__ void ldsm_x4(uint32_t& r0, uint32_t& r1,
                                        uint32_t& r2, uint32_t& r3, uint32_t a) {
    asm volatile("ldmatrix.sync.aligned.m8n8.x4.shared.b16 {%0,%1,%2,%3}, [%4];"
                 : "=r"(r0), "=r"(r1), "=r"(r2), "=r"(r3) : "r"(a));
}
__device__ __forceinline__ void ldsm_x4_t(uint32_t& r0, uint32_t& r1,
                                          uint32_t& r2, uint32_t& r3, uint32_t a) {
    asm volatile("ldmatrix.sync.aligned.m8n8.x4.trans.shared.b16 {%0,%1,%2,%3}, [%4];"
                 : "=r"(r0), "=r"(r1), "=r"(r2), "=r"(r3) : "r"(a));
}

// ---------------------------------------------------------------------------
// Fused weight transpose+bf16: one launch, 4992 tile-blocks over 9 segments.
// dst[n][k] = bf16(src[k][n])
// ---------------------------------------------------------------------------
__global__ void transpose_all(uint16_t* __restrict__ gw,
    const float* s0, const float* s1, const float* s2, const float* s3,
    const float* s4, const float* s5, const float* s6, const float* s7,
    const float* s8) {
    __shared__ float t[32][33];
    int tb = blockIdx.x;
    const float* src; uint16_t* dst; int K, N, tn;
    if (tb < 1024)      { src = s0; dst = gw + GWQ;  K = 1024; N = 1024; tn = tb; }
    else if (tb < 1280) { src = s1; dst = gw + GKV;  K = 1024; N = 256;  tn = tb - 1024; }
    else if (tb < 1344) { src = s2; dst = gw + GKUP; K = 256;  N = 256;  tn = tb - 1280; }
    else if (tb < 1408) { src = s3; dst = gw + GVUP; K = 256;  N = 256;  tn = tb - 1344; }
    else if (tb < 2432) { src = s4; dst = gw + GWO;  K = 1024; N = 1024; tn = tb - 1408; }
    else if (tb < 3456) { src = s5; dst = gw + LWQ;  K = 1024; N = 1024; tn = tb - 2432; }
    else if (tb < 3712) { src = s6; dst = gw + LWK;  K = 1024; N = 256;  tn = tb - 3456; }
    else if (tb < 3968) { src = s7; dst = gw + LWV;  K = 1024; N = 256;  tn = tb - 3712; }
    else                { src = s8; dst = gw + LWO;  K = 1024; N = 1024; tn = tb - 3968; }
    int tilesN = N >> 5;
    int n0 = (tn % tilesN) * 32, k0 = (tn / tilesN) * 32;
    int x = threadIdx.x, y = threadIdx.y;
    #pragma unroll
    for (int i = 0; i < 32; i += 8)
        t[y + i][x] = src[(size_t)(k0 + y + i) * N + n0 + x];
    __syncthreads();
    #pragma unroll
    for (int i = 0; i < 32; i += 8)
        dst[(size_t)(n0 + y + i) * K + k0 + x] = f2bf(t[x][y + i]);
}

// ---------------------------------------------------------------------------
// RMSNorm: fp32 in -> bf16 out
// ---------------------------------------------------------------------------
__global__ void rmsnorm_kernel(const float* __restrict__ x,
                               const float* __restrict__ w,
                               uint16_t* __restrict__ y) {
    int row = blockIdx.x;
    int tid = threadIdx.x;
    const float4* xr = (const float4*)(x + (size_t)row * DMODEL);
    float4 v = xr[tid];
    float ss = v.x * v.x + v.y * v.y + v.z * v.z + v.w * v.w;
    __shared__ float red[256];
    red[tid] = ss;
    __syncthreads();
    #pragma unroll
    for (int o = 128; o > 0; o >>= 1) {
        if (tid < o) red[tid] += red[tid + o];
        __syncthreads();
    }
    float r = rsqrtf(red[0] / (float)DMODEL + 1e-6f);
    float4 wv = ((const float4*)w)[tid];
    uint32_t* yw = (uint32_t*)(y + (size_t)row * DMODEL);
    yw[2 * tid]     = pack_bf16(v.x * r * wv.x, v.y * r * wv.y);
    yw[2 * tid + 1] = pack_bf16(v.z * r * wv.z, v.w * r * wv.w);
}

// ---------------------------------------------------------------------------
// Segmented BF16 GEMM: cp.async 2-stage + ldmatrix fragments.
// A bf16 [M][K]; B bf16 [nseg][K] (pre-transposed); warp layout 2m x 4n.
// ---------------------------------------------------------------------------
template<int BM, int BN, int BK>
__global__ __launch_bounds__(256, 2)
void bgemm(const uint16_t* __restrict__ A,
           const uint16_t* __restrict__ B0, void* C0, int n0,
           const uint16_t* __restrict__ B1, void* C1, int n1,
           const uint16_t* __restrict__ B2, void* C2, int n2,
           const float* __restrict__ R, int K, int bfout) {
    constexpr int PW  = BK / 2 + 4;       // word pitch
    constexpr int WM  = BM / 2;
    constexpr int WN  = BN / 4;
    constexpr int MT  = WM / 16;
    constexpr int NT  = WN / 8;
    constexpr int ACP = BM * 4 / 256;     // cp16 per thread per stage
    constexpr int BCP = BN * 4 / 256;

    extern __shared__ uint32_t smw[];
    uint32_t (*As)[BM][PW] = (uint32_t(*)[BM][PW])smw;
    uint32_t (*Bs)[BN][PW] = (uint32_t(*)[BN][PW])(smw + 2 * BM * PW);

    int tid  = threadIdx.x;
    int wid  = tid >> 5;
    int lane = tid & 31;
    int g    = lane >> 2;
    int cq   = lane & 3;
    int l15  = lane & 15;
    int h4   = (lane >> 4) * 4;
    int wm   = (wid & 1) * WM;
    int wn   = (wid >> 1) * WN;
    int r0   = blockIdx.y * BM;
    int c0   = blockIdx.x * BN;

    const uint16_t* Bseg;
    void* Cseg;
    int nseg, segc, segi;
    if (c0 < n0)           { Bseg = B0; Cseg = C0; nseg = n0; segc = c0; segi = 0; }
    else if (c0 < n0 + n1) { Bseg = B1; Cseg = C1; nseg = n1; segc = c0 - n0; segi = 1; }
    else                   { Bseg = B2; Cseg = C2; nseg = n2; segc = c0 - n0 - n1; segi = 2; }
    bool bfo = (bfout >> segi) & 1;

    float acc[MT][NT][4];
    #pragma unroll
    for (int t = 0; t < MT; t++)
        #pragma unroll
        for (int u = 0; u < NT; u++)
            #pragma unroll
            for (int i = 0; i < 4; i++) acc[t][u][i] = 0.0f;

    uint32_t aBase = s2u(&As[0][0][0]);
    uint32_t bBase = s2u(&Bs[0][0][0]);

    // stage 0
    #pragma unroll
    for (int t = 0; t < ACP; t++) {
        int idx = tid + t * 256;
        int ar = idx >> 2, ch = idx & 3;
        cp16(s2u(&As[0][ar][ch * 4]), A + (size_t)(r0 + ar) * K + ch * 8);
    }
    #pragma unroll
    for (int t = 0; t < BCP; t++) {
        int idx = tid + t * 256;
        int br = idx >> 2, ch = idx & 3;
        cp16(s2u(&Bs[0][br][ch * 4]), Bseg + (size_t)(segc + br) * K + ch * 8);
    }
    cp_commit();

    int NKB = K / BK;
    for (int kb = 0; kb < NKB; kb++) {
        int b = kb & 1;
        if (kb + 1 < NKB) {
            int k0 = (kb + 1) * BK;
            #pragma unroll
            for (int t = 0; t < ACP; t++) {
                int idx = tid + t * 256;
                int ar = idx >> 2, ch = idx & 3;
                cp16(s2u(&As[b ^ 1][ar][ch * 4]),
                     A + (size_t)(r0 + ar) * K + k0 + ch * 8);
            }
            #pragma unroll
            for (int t = 0; t < BCP; t++) {
                int idx = tid + t * 256;
                int br = idx >> 2, ch = idx & 3;
                cp16(s2u(&Bs[b ^ 1][br][ch * 4]),
                     Bseg + (size_t)(segc + br) * K + k0 + ch * 8);
            }
            cp_commit();
            cp_wait<1>();
        } else {
            cp_wait<0>();
        }
        __syncthreads();

        uint32_t aB = aBase + (uint32_t)(b * BM * PW * 4);
        uint32_t bB = bBase + (uint32_t)(b * BN * PW * 4);

        #pragma unroll
        for (int k16 = 0; k16 < BK / 16; k16++) {
            int kw = k16 * 8 + h4;
            uint32_t af[MT][4];
            #pragma unroll
            for (int t = 0; t < MT; t++)
                ldsm_x4(af[t][0], af[t][1], af[t][2], af[t][3],
                        aB + (uint32_t)(((wm + 16 * t + l15) * PW + kw) * 4));
            uint32_t bf[NT][2];
            #pragma unroll
            for (int u2 = 0; u2 < NT / 2; u2++)
                ldsm_x4(bf[2 * u2][0], bf[2 * u2 + 1][0],
                        bf[2 * u2][1], bf[2 * u2 + 1][1],
                        bB + (uint32_t)(((wn + 16 * u2 + l15) * PW + kw) * 4));
            #pragma unroll
            for (int t = 0; t < MT; t++)
                #pragma unroll
                for (int u = 0; u < NT; u++)
                    mma_bf16(acc[t][u], af[t][0], af[t][1], af[t][2], af[t][3],
                             bf[u][0], bf[u][1]);
        }
        __syncthreads();
    }

    #pragma unroll
    for (int t = 0; t < MT; t++) {
        int row = r0 + wm + 16 * t + g;
        #pragma unroll
        for (int u = 0; u < NT; u++) {
            int col = segc + wn + 8 * u + 2 * cq;
            size_t off0 = (size_t)row * nseg + col;
            size_t off1 = (size_t)(row + 8) * nseg + col;
            if (bfo) {
                uint16_t* Cb = (uint16_t*)Cseg;
                *(uint32_t*)(Cb + off0) = pack_bf16(acc[t][u][0], acc[t][u][1]);
                *(uint32_t*)(Cb + off1) = pack_bf16(acc[t][u][2], acc[t][u][3]);
            } else {
                float* Cf = (float*)Cseg;
                float2 r0v = make_float2(0.f, 0.f), r1v = make_float2(0.f, 0.f);
                if (R) {
                    r0v = *(const float2*)(R + off0);
                    r1v = *(const float2*)(R + off1);
                }
                *(float2*)(Cf + off0) = make_float2(acc[t][u][0] + r0v.x,
                                                    acc[t][u][1] + r0v.y);
                *(float2*)(Cf + off1) = make_float2(acc[t][u][2] + r1v.x,
                                                    acc[t][u][3] + r1v.y);
            }
        }
    }
}

// ---------------------------------------------------------------------------
// Fast RoPE + qk_norm on bf16 q/k: one block per s, 20 warps = 20 heads.
// Q scaled by 1/8 (exact pow2; folded softmax scale).
// ---------------------------------------------------------------------------
__global__ __launch_bounds__(640)
void rope_qknorm_fast(uint16_t* __restrict__ q, uint16_t* __restrict__ k,
                      float base) {
    __shared__ float scs[32], ssn[32];
    int s   = blockIdx.x;
    int tid = threadIdx.x;
    int w   = tid >> 5;
    int i   = tid & 31;

    if (tid < 32) {
        float invf = powf(base, -((float)(2 * tid) / (float)HDIM));
        float ang = (float)s * invf;
        sincosf(ang, &ssn[tid], &scs[tid]);
    }
    __syncthreads();

    uint32_t* p;
    float scale;
    if (w < NH) { p = (uint32_t*)(q + (size_t)s * DMODEL + w * HDIM); scale = 0.125f; }
    else        { p = (uint32_t*)(k + (size_t)s * LATD + (w - NH) * HDIM); scale = 1.0f; }

    uint32_t xw = p[i];
    float xe = bf_lo(xw), xo = bf_hi(xw);
    float cs = scs[i], sn = ssn[i];
    float re = xe * cs - xo * sn;
    float ro = xe * sn + xo * cs;

    float ss = re * re + ro * ro;
    #pragma unroll
    for (int o = 16; o > 0; o >>= 1)
        ss += __shfl_xor_sync(0xffffffffu, ss, o);

    float r = rsqrtf(ss / (float)HDIM + 1e-6f) * scale;
    p[i] = pack_bf16(re * r, ro * r);
}

// ---------------------------------------------------------------------------
// BF16 mma flash attention. Block = (64-q tile, head), 128 threads / 4 warps.
// ldmatrix K (non-trans) + V (trans, direct from [key][hd]); P stays in regs.
// SMEM words (pitch 36): Qs[64] Ks[2][64] Vs[2][64] = 46080 B
// ---------------------------------------------------------------------------
#define APW 36
__global__ __launch_bounds__(128, 3)
void fattn_mma(const uint16_t* __restrict__ Q, const uint16_t* __restrict__ K,
               const uint16_t* __restrict__ V, uint16_t* __restrict__ O,
               int win) {
    extern __shared__ uint32_t smw[];
    uint32_t (*Qs)[APW]     = (uint32_t(*)[APW])smw;
    uint32_t (*Ks)[64][APW] = (uint32_t(*)[64][APW])(smw + 64 * APW);
    uint32_t (*Vs)[64][APW] = (uint32_t(*)[64][APW])(smw + 3 * 64 * APW);

    int qt  = gridDim.x - 1 - blockIdx.x;   // heavy tiles first
    int h   = blockIdx.y;
    int kvh = h >> 2;
    int tid = threadIdx.x;
    int wid = tid >> 5;
    int lane = tid & 31;
    int g   = lane >> 2;
    int cq  = lane & 3;
    int l15 = lane & 15;
    int h4  = (lane >> 4) * 4;
    int m0  = wid * 16;
    int q0  = qt * 64;

    int jt0 = 0;
    if (win > 0) { jt0 = qt - 4; if (jt0 < 0) jt0 = 0; }

    // stage first K/V tile
    {
        int j0 = jt0 * 64;
        #pragma unroll
        for (int t = 0; t < 4; t++) {
            int idx = tid + t * 128;
            int jj = idx >> 3, ch = idx & 7;
            cp16(s2u(&Ks[0][jj][ch * 4]),
                 K + (size_t)(j0 + jj) * LATD + kvh * HDIM + ch * 8);
            cp16(s2u(&Vs[0][jj][ch * 4]),
                 V + (size_t)(j0 + jj) * LATD + kvh * HDIM + ch * 8);
        }
        cp_commit();
    }

    // stage Q (bf16, pre-scaled by 1/8)
    #pragma unroll
    for (int t = 0; t < 4; t++) {
        int idx = tid + t * 128;
        int qi = idx >> 3, ch = idx & 7;
        *(uint4*)&Qs[qi][ch * 4] =
            *(const uint4*)(Q + (size_t)(q0 + qi) * DMODEL + h * HDIM + ch * 8);
    }
    __syncthreads();

    // hoist Q fragments via ldmatrix (4 k16 windows over HDIM)
    uint32_t qBase = s2u(&Qs[0][0]);
    uint32_t qf[4][4];
    #pragma unroll
    for (int k16 = 0; k16 < 4; k16++)
        ldsm_x4(qf[k16][0], qf[k16][1], qf[k16][2], qf[k16][3],
                qBase + (uint32_t)(((m0 + l15) * APW + k16 * 8 + h4) * 4));

    float o[8][4];
    #pragma unroll
    for (int u = 0; u < 8; u++)
        #pragma unroll
        for (int i = 0; i < 4; i++) o[u][i] = 0.0f;
    float mrow0 = -60.0f, mrow1 = -60.0f;
    float lrow0 = 0.0f,   lrow1 = 0.0f;

    int row0 = q0 + m0 + g;
    int row1 = row0 + 8;
    uint32_t kBase = s2u(&Ks[0][0][0]);
    uint32_t vBase = s2u(&Vs[0][0][0]);

    for (int jt = jt0; jt <= qt; jt++) {
        int b = (jt - jt0) & 1;
        if (jt < qt) {
            int j0 = (jt + 1) * 64;
            #pragma unroll
            for (int t = 0; t < 4; t++) {
                int idx = tid + t * 128;
                int jj = idx >> 3, ch = idx & 7;
                cp16(s2u(&Ks[b ^ 1][jj][ch * 4]),
                     K + (size_t)(j0 + jj) * LATD + kvh * HDIM + ch * 8);
                cp16(s2u(&Vs[b ^ 1][jj][ch * 4]),
                     V + (size_t)(j0 + jj) * LATD + kvh * HDIM + ch * 8);
            }
            cp_commit();
            cp_wait<1>();
        } else {
            cp_wait<0>();
        }
        __syncthreads();

        int j0 = jt * 64;
        uint32_t kB = kBase + (uint32_t)(b * 64 * APW * 4);
        uint32_t vB = vBase + (uint32_t)(b * 64 * APW * 4);

        // S = Q K^T  (keys = n dim; B frags non-trans from [key][hd])
        float s[8][4];
        #pragma unroll
        for (int u = 0; u < 8; u++)
            #pragma unroll
            for (int i = 0; i < 4; i++) s[u][i] = 0.0f;

        #pragma unroll
        for (int k16 = 0; k16 < 4; k16++) {
            int kw = k16 * 8 + h4;
            #pragma unroll
            for (int u2 = 0; u2 < 4; u2++) {
                uint32_t b00, b01, b10, b11;
                ldsm_x4(b00, b10, b01, b11,
                        kB + (uint32_t)(((u2 * 16 + l15) * APW + kw) * 4));
                mma_bf16(s[2 * u2],     qf[k16][0], qf[k16][1], qf[k16][2],
                         qf[k16][3], b00, b01);
                mma_bf16(s[2 * u2 + 1], qf[k16][0], qf[k16][1], qf[k16][2],
                         qf[k16][3], b10, b11);
            }
        }

        // mask
        #pragma unroll
        for (int u = 0; u < 8; u++) {
            int col = j0 + u * 8 + 2 * cq;
            #pragma unroll
            for (int i = 0; i < 4; i++) {
                int q  = (i < 2) ? row0 : row1;
                int kj = col + (i & 1);
                bool vis = (kj <= q) && (win == 0 || (q - kj) < win);
                if (!vis) s[u][i] = -1e30f;
            }
        }

        // online softmax
        float rm0 = -1e30f, rm1 = -1e30f;
        #pragma unroll
        for (int u = 0; u < 8; u++) {
            rm0 = fmaxf(rm0, fmaxf(s[u][0], s[u][1]));
            rm1 = fmaxf(rm1, fmaxf(s[u][2], s[u][3]));
        }
        #pragma unroll
        for (int off = 1; off <= 2; off <<= 1) {
            rm0 = fmaxf(rm0, __shfl_xor_sync(0xffffffffu, rm0, off));
            rm1 = fmaxf(rm1, __shfl_xor_sync(0xffffffffu, rm1, off));
        }
        float mn0 = fmaxf(mrow0, rm0);
        float mn1 = fmaxf(mrow1, rm1);
        float al0 = __expf(mrow0 - mn0);
        float al1 = __expf(mrow1 - mn1);
        float rs0 = 0.0f, rs1 = 0.0f;
        #pragma unroll
        for (int u = 0; u < 8; u++) {
            float p0 = __expf(s[u][0] - mn0);
            float p1 = __expf(s[u][1] - mn0);
            float p2 = __expf(s[u][2] - mn1);
            float p3 = __expf(s[u][3] - mn1);
            s[u][0] = p0; s[u][1] = p1; s[u][2] = p2; s[u][3] = p3;
            rs0 += p0 + p1;
            rs1 += p2 + p3;
        }
        #pragma unroll
        for (int off = 1; off <= 2; off <<= 1) {
            rs0 += __shfl_xor_sync(0xffffffffu, rs0, off);
            rs1 += __shfl_xor_sync(0xffffffffu, rs1, off);
        }
        lrow0 = lrow0 * al0 + rs0;
        lrow1 = lrow1 * al1 + rs1;
        mrow0 = mn0;
        mrow1 = mn1;
        #pragma unroll
        for (int u = 0; u < 8; u++) {
            o[u][0] *= al0; o[u][1] *= al0;
            o[u][2] *= al1; o[u][3] *= al1;
        }

        // P fragments directly from S accumulators (no SMEM round-trip)
        uint32_t pf[4][4];
        #pragma unroll
        for (int w = 0; w < 4; w++) {
            pf[w][0] = pack_bf16(s[2 * w][0],     s[2 * w][1]);
            pf[w][1] = pack_bf16(s[2 * w][2],     s[2 * w][3]);
            pf[w][2] = pack_bf16(s[2 * w + 1][0], s[2 * w + 1][1]);
            pf[w][3] = pack_bf16(s[2 * w + 1][2], s[2 * w + 1][3]);
        }

        // O += P @ V  (V trans-ldmatrix from [key][hd])
        #pragma unroll
        for (int w = 0; w < 4; w++) {
            #pragma unroll
            for (int u2 = 0; u2 < 4; u2++) {
                uint32_t c00, c01, c10, c11;
                ldsm_x4_t(c00, c01, c10, c11,
                          vB + (uint32_t)(((w * 16 + l15) * APW + u2 * 8 + h4) * 4));
                mma_bf16(o[2 * u2],     pf[w][0], pf[w][1], pf[w][2], pf[w][3],
                         c00, c01);
                mma_bf16(o[2 * u2 + 1], pf[w][0], pf[w][1], pf[w][2], pf[w][3],
                         c10, c11);
            }
        }
        __syncthreads();
    }

    float inv0 = 1.0f / lrow0;
    float inv1 = 1.0f / lrow1;
    #pragma unroll
    for (int u = 0; u < 8; u++) {
        int col = u * 8 + 2 * cq;
        *(uint32_t*)(O + (size_t)row0 * DMODEL + h * HDIM + col) =
            pack_bf16(o[u][0] * inv0, o[u][1] * inv0);
        *(uint32_t*)(O + (size_t)row1 * DMODEL + h * HDIM + col) =
            pack_bf16(o[u][2] * inv1, o[u][3] * inv1);
    }
}

// ---------------------------------------------------------------------------
// Launch
// ---------------------------------------------------------------------------
extern "C" void kernel_launch(void* const* d_in, const int* in_sizes, int n_in,
                              void* d_out, int out_size) {
    (void)in_sizes; (void)n_in; (void)out_size;

    const float* hidden   = (const float*)d_in[0];
    const float* norm1_w  = (const float*)d_in[1];
    const float* norm2_w  = (const float*)d_in[2];
    const float* w_g_wq   = (const float*)d_in[3];
    const float* w_g_kvdn = (const float*)d_in[4];
    const float* w_g_k_up = (const float*)d_in[5];
    const float* w_g_v_up = (const float*)d_in[6];
    const float* w_g_wo   = (const float*)d_in[7];
    const float* w_l_wq   = (const float*)d_in[8];
    const float* w_l_wk   = (const float*)d_in[9];
    const float* w_l_wv   = (const float*)d_in[10];
    const float* w_l_wo   = (const float*)d_in[11];
    float* out = (float*)d_out;

    uint16_t *x1, *q, *lat, *k, *v, *attn, *gw;
    cudaGetSymbolAddress((void**)&x1,   g_x1);
    cudaGetSymbolAddress((void**)&q,    g_q);
    cudaGetSymbolAddress((void**)&lat,  g_lat);
    cudaGetSymbolAddress((void**)&k,    g_k);
    cudaGetSymbolAddress((void**)&v,    g_v);
    cudaGetSymbolAddress((void**)&attn, g_attn);
    cudaGetSymbolAddress((void**)&gw,   g_w);

    const int GEMM128_SMEM = 2 * (128 * 20 + 128 * 20) * 4;  // 40960
    const int GEMM64_SMEM  = 2 * (64 * 20 + 64 * 20) * 4;    // 20480
    const int ATTN_SMEM    = 5 * 64 * APW * 4;               // 46080

    cudaFuncSetAttribute(bgemm<128, 128, 32>,
                         cudaFuncAttributeMaxDynamicSharedMemorySize, GEMM128_SMEM);
    cudaFuncSetAttribute(bgemm<64, 64, 32>,
                         cudaFuncAttributeMaxDynamicSharedMemorySize, GEMM64_SMEM);
    cudaFuncSetAttribute(fattn_mma,
                         cudaFuncAttributeMaxDynamicSharedMemorySize, ATTN_SMEM);

    dim3 gridAttn(SEQ / 64, NH);

    // ---- Pre-pass: single fused weight transpose+convert ----
    transpose_all<<<4992, dim3(32, 8)>>>(gw,
        w_g_wq, w_g_kvdn, w_g_k_up, w_g_v_up, w_g_wo,
        w_l_wq, w_l_wk, w_l_wv, w_l_wo);

    // ---- Layer 1: global latent attention ----
    rmsnorm_kernel<<<SEQ, 256>>>(hidden, norm1_w, x1);
    bgemm<128, 128, 32><<<dim3(10, 16), 256, GEMM128_SMEM>>>(
        x1, gw + GWQ, q, DMODEL, gw + GKV, lat, LATD,
        nullptr, nullptr, 0, nullptr, DMODEL, /*bfout=*/3);
    bgemm<64, 64, 32><<<dim3(8, 32), 256, GEMM64_SMEM>>>(
        lat, gw + GKUP, k, LATD, gw + GVUP, v, LATD,
        nullptr, nullptr, 0, nullptr, LATD, /*bfout=*/3);
    rope_qknorm_fast<<<SEQ, 640>>>(q, k, 1000000.0f);
    fattn_mma<<<gridAttn, 128, ATTN_SMEM>>>(q, k, v, attn, /*win=*/0);
    bgemm<128, 128, 32><<<dim3(8, 16), 256, GEMM128_SMEM>>>(
        attn, gw + GWO, out, DMODEL, nullptr, nullptr, 0,
        nullptr, nullptr, 0, hidden, DMODEL, /*bfout=*/0);

    // ---- Layer 2: local GQA attention ----
    rmsnorm_kernel<<<SEQ, 256>>>(out, norm2_w, x1);
    bgemm<128, 128, 32><<<dim3(12, 16), 256, GEMM128_SMEM>>>(
        x1, gw + LWQ, q, DMODEL, gw + LWK, k, LATD,
        gw + LWV, v, LATD, nullptr, DMODEL, /*bfout=*/7);
    rope_qknorm_fast<<<SEQ, 640>>>(q, k, 10000.0f);
    fattn_mma<<<gridAttn, 128, ATTN_SMEM>>>(q, k, v, attn, /*win=*/WINSZ);
    bgemm<128, 128, 32><<<dim3(8, 16), 256, GEMM128_SMEM>>>(
        attn, gw + LWO, out, DMODEL, nullptr, nullptr, 0,
        nullptr, nullptr, 0, out, DMODEL, /*bfout=*/0);
}